// round 6
// baseline (speedup 1.0000x reference)
#include <cuda_runtime.h>
#include <cuda_fp16.h>
#include <cstdint>

// ---------------------------------------------------------------------------
// FSNet: emb -> biGRU(2 layer) encoder -> broadcast -> biGRU(2 layer) decoder
//        -> fc head (64x20)  and  reconstruction GEMM (6400x10000x256)
// GRU path fp32 (f32x2 packed FMA), 2 batches per block sharing weight regs.
// Reconstruction GEMM fp16 HMMA (fp32 acc), cp.async + ldmatrix.
// ---------------------------------------------------------------------------

#define B_    64
#define T_    100
#define H_    128
#define G3H   384            // 3*H
#define BT    (B_*T_)        // 6400
#define VOCAB 10000
#define NCLS  20

// ------------------------------ scratch ------------------------------------
__device__ __align__(16) float  g_E   [BT * 128];     // embedded input
__device__ __align__(16) float  g_GI  [BT * 768];     // input-gate preacts
__device__ __align__(16) float  g_GIc [B_ * 768];     // dec layer0 const gi
__device__ __align__(16) float  g_Y0  [BT * 256];     // layer0 outputs
__device__ __align__(16) __half g_RECh[BT * 256];     // rec_seq in fp16
__device__ __align__(16) __half g_Wh  [VOCAB * 256];  // rec_W in fp16
__device__ __align__(16) float  g_ench[B_ * 512];
__device__ __align__(16) float  g_dech[B_ * 512];
__device__ int g_is32;

// --------------------------- helpers ---------------------------------------
__device__ __forceinline__ unsigned long long pk2(float x, float y) {
    unsigned long long r;
    asm("mov.b64 %0, {%1, %2};" : "=l"(r)
        : "r"(__float_as_uint(x)), "r"(__float_as_uint(y)));
    return r;
}
__device__ __forceinline__ void upk(unsigned long long v, float& x, float& y) {
    unsigned int a, b;
    asm("mov.b64 {%0, %1}, %2;" : "=r"(a), "=r"(b) : "l"(v));
    x = __uint_as_float(a); y = __uint_as_float(b);
}
__device__ __forceinline__ unsigned long long f2fma(unsigned long long a,
                                                    unsigned long long b,
                                                    unsigned long long c) {
    unsigned long long d;
    asm("fma.rn.f32x2 %0, %1, %2, %3;" : "=l"(d) : "l"(a), "l"(b), "l"(c));
    return d;
}
__device__ __forceinline__ float fast_sigm(float x) {
    float e;
    asm("ex2.approx.f32 %0, %1;" : "=f"(e) : "f"(-1.4426950408889634f * x));
    float r;
    asm("rcp.approx.f32 %0, %1;" : "=f"(r) : "f"(1.0f + e));
    return r;
}
__device__ __forceinline__ float fast_tanh(float x) {
    return 2.0f * fast_sigm(2.0f * x) - 1.0f;
}
__device__ __forceinline__ uint32_t smaddr(const void* p) {
    return (uint32_t)__cvta_generic_to_shared(p);
}
__device__ __forceinline__ void cp16(uint32_t dst, const void* src) {
    asm volatile("cp.async.cg.shared.global [%0], [%1], 16;"
                 :: "r"(dst), "l"(src));
}

// ------------------------- dtype detect (int32 vs int64) --------------------
__global__ void detect_k(const unsigned int* p) {
    __shared__ int s;
    if (threadIdx.x == 0) s = 0;
    __syncthreads();
    if (p[2 * threadIdx.x + 1] != 0) atomicOr(&s, 1);
    __syncthreads();
    if (threadIdx.x == 0) g_is32 = s;
}

// ------------------------------- embedding ----------------------------------
__global__ void embed_k(const void* xraw, const float* __restrict__ emb) {
    int s = blockIdx.x * blockDim.x + threadIdx.x;
    if (s >= BT * 32) return;
    int i = s >> 5, t = s & 31;
    long long xi;
    if (g_is32) xi = ((const int*)xraw)[i];
    else        xi = ((const long long*)xraw)[i];
    int r = (int)xi;
    if (r > 9999) r = 9999;
    if (r < 0)    r = 0;
    ((float4*)g_E)[s] = ((const float4*)emb)[r * 32 + t];
}

// -------------------------- fp32 -> fp16 convert ----------------------------
__global__ void cvt_k(const float* __restrict__ src, __half* __restrict__ dst,
                      int n2) {
    int i = blockIdx.x * blockDim.x + threadIdx.x;
    if (i >= n2) return;
    float2 v = ((const float2*)src)[i];
    ((__half2*)dst)[i] = __floats2half2_rn(v.x, v.y);
}

// ------------------------------ tiled fp32 GEMM -----------------------------
// C[M,N] = A[M,K] @ B[N,K]^T + bias[N].
#define BM 128
#define BN 128
#define BKt 16

__global__ void __launch_bounds__(256) gemm_bt_k(
    const float* __restrict__ A, const float* __restrict__ Bm,
    const float* __restrict__ bias, float* __restrict__ C,
    int M, int N, int K)
{
    __shared__ __align__(16) float As[BKt][BM + 4];
    __shared__ __align__(16) float Bs[BKt][BN + 4];
    int tid = threadIdx.x;
    int tx = tid & 15, ty = tid >> 4;
    int n0 = blockIdx.x * BN, m0 = blockIdx.y * BM;

    unsigned long long acc[4][8];
#pragma unroll
    for (int i = 0; i < 4; i++)
#pragma unroll
        for (int j = 0; j < 8; j++) acc[i][j] = 0ull;

    for (int kk = 0; kk < K; kk += BKt) {
#pragma unroll
        for (int q = 0; q < 2; q++) {
            int s = tid + q * 256;
            int row = s >> 2, kq = s & 3;
            float4 va = make_float4(0.f, 0.f, 0.f, 0.f);
            int gm = m0 + row;
            if (gm < M) va = *(const float4*)(A + (size_t)gm * K + kk + kq * 4);
            As[kq * 4 + 0][row] = va.x; As[kq * 4 + 1][row] = va.y;
            As[kq * 4 + 2][row] = va.z; As[kq * 4 + 3][row] = va.w;
            float4 vb = make_float4(0.f, 0.f, 0.f, 0.f);
            int gn = n0 + row;
            if (gn < N) vb = *(const float4*)(Bm + (size_t)gn * K + kk + kq * 4);
            Bs[kq * 4 + 0][row] = vb.x; Bs[kq * 4 + 1][row] = vb.y;
            Bs[kq * 4 + 2][row] = vb.z; Bs[kq * 4 + 3][row] = vb.w;
        }
        __syncthreads();
#pragma unroll
        for (int k = 0; k < BKt; k++) {
            const unsigned long long* ap =
                (const unsigned long long*)&As[k][ty * 8];
            unsigned long long a0 = ap[0], a1 = ap[1], a2 = ap[2], a3 = ap[3];
            float4 b0 = *(const float4*)&Bs[k][tx * 8];
            float4 b1 = *(const float4*)&Bs[k][tx * 8 + 4];
            float bv[8] = {b0.x, b0.y, b0.z, b0.w, b1.x, b1.y, b1.z, b1.w};
#pragma unroll
            for (int j = 0; j < 8; j++) {
                unsigned long long bd = pk2(bv[j], bv[j]);
                acc[0][j] = f2fma(a0, bd, acc[0][j]);
                acc[1][j] = f2fma(a1, bd, acc[1][j]);
                acc[2][j] = f2fma(a2, bd, acc[2][j]);
                acc[3][j] = f2fma(a3, bd, acc[3][j]);
            }
        }
        __syncthreads();
    }

    float bvv[8];
#pragma unroll
    for (int j = 0; j < 8; j++) {
        int gc = n0 + tx * 8 + j;
        bvv[j] = (gc < N) ? bias[gc] : 0.f;
    }
    int gc0 = n0 + tx * 8;
    bool c0ok = (gc0 < N), c1ok = (gc0 + 4 < N);
#pragma unroll
    for (int ip = 0; ip < 4; ip++) {
        float lo[8], hi[8];
#pragma unroll
        for (int j = 0; j < 8; j++) {
            upk(acc[ip][j], lo[j], hi[j]);
            lo[j] += bvv[j]; hi[j] += bvv[j];
        }
        int r0 = m0 + ty * 8 + 2 * ip;
        if (r0 < M) {
            float* cp = C + (size_t)r0 * N + gc0;
            if (c0ok) *(float4*)cp       = make_float4(lo[0], lo[1], lo[2], lo[3]);
            if (c1ok) *(float4*)(cp + 4) = make_float4(lo[4], lo[5], lo[6], lo[7]);
        }
        if (r0 + 1 < M) {
            float* cp = C + (size_t)(r0 + 1) * N + gc0;
            if (c0ok) *(float4*)cp       = make_float4(hi[0], hi[1], hi[2], hi[3]);
            if (c1ok) *(float4*)(cp + 4) = make_float4(hi[4], hi[5], hi[6], hi[7]);
        }
    }
}

// ----------------------- fp16 HMMA GEMM (rec head) --------------------------
__global__ void __launch_bounds__(256, 2) gemm_h_k(
    const __half* __restrict__ A, const __half* __restrict__ Bm,
    const float* __restrict__ bias, float* __restrict__ C, int N)
{
    const int K = 256;
    __shared__ __align__(16) __half Asm[2][128 * 32];
    __shared__ __align__(16) __half Bsm[2][128 * 32];

    int tid = threadIdx.x, lane = tid & 31, wid = tid >> 5;
    int wm = wid & 1, wn = wid >> 1;
    int m0 = blockIdx.y * 128, n0 = blockIdx.x * 128;

    float c[4][4][4];
#pragma unroll
    for (int mi = 0; mi < 4; mi++)
#pragma unroll
        for (int ni = 0; ni < 4; ni++)
#pragma unroll
            for (int r = 0; r < 4; r++) c[mi][ni][r] = 0.f;

    int lr = tid >> 1;
    int lc0 = (tid & 1) * 2;
    int bn = n0 + lr; if (bn > N - 1) bn = N - 1;
    const __half* Abase = A + (size_t)(m0 + lr) * K;
    const __half* Bbase = Bm + (size_t)bn * K;

#define SOFF(r, ch) ((r) * 32 + (((ch) ^ ((r) & 3)) << 3))

#pragma unroll
    for (int c2 = 0; c2 < 2; c2++) {
        int ch = lc0 + c2;
        cp16(smaddr(&Asm[0][SOFF(lr, ch)]), Abase + ch * 8);
        cp16(smaddr(&Bsm[0][SOFF(lr, ch)]), Bbase + ch * 8);
    }
    asm volatile("cp.async.commit_group;");

    int buf = 0;
    for (int kc = 0; kc < K / 32; kc++) {
        asm volatile("cp.async.wait_group 0;");
        __syncthreads();
        if (kc + 1 < K / 32) {
            int kk = (kc + 1) * 32;
#pragma unroll
            for (int c2 = 0; c2 < 2; c2++) {
                int ch = lc0 + c2;
                cp16(smaddr(&Asm[buf ^ 1][SOFF(lr, ch)]), Abase + kk + ch * 8);
                cp16(smaddr(&Bsm[buf ^ 1][SOFF(lr, ch)]), Bbase + kk + ch * 8);
            }
            asm volatile("cp.async.commit_group;");
        }
#pragma unroll
        for (int ks = 0; ks < 2; ks++) {
            unsigned a[4][4], b[2][4];
#pragma unroll
            for (int mi = 0; mi < 4; mi++) {
                int row = wm * 64 + mi * 16 + (lane & 15);
                int ch  = ks * 2 + (lane >> 4);
                uint32_t ad = smaddr(&Asm[buf][SOFF(row, ch)]);
                asm volatile(
                    "ldmatrix.sync.aligned.m8n8.x4.shared.b16 {%0,%1,%2,%3}, [%4];"
                    : "=r"(a[mi][0]), "=r"(a[mi][1]), "=r"(a[mi][2]), "=r"(a[mi][3])
                    : "r"(ad));
            }
#pragma unroll
            for (int nj = 0; nj < 2; nj++) {
                int row = wn * 32 + nj * 16 + (lane & 7) + (lane >> 4) * 8;
                int ch  = ks * 2 + ((lane >> 3) & 1);
                uint32_t bd = smaddr(&Bsm[buf][SOFF(row, ch)]);
                asm volatile(
                    "ldmatrix.sync.aligned.m8n8.x4.shared.b16 {%0,%1,%2,%3}, [%4];"
                    : "=r"(b[nj][0]), "=r"(b[nj][1]), "=r"(b[nj][2]), "=r"(b[nj][3])
                    : "r"(bd));
            }
#pragma unroll
            for (int mi = 0; mi < 4; mi++)
#pragma unroll
                for (int ni = 0; ni < 4; ni++) {
                    unsigned bb0 = b[ni >> 1][(ni & 1) * 2];
                    unsigned bb1 = b[ni >> 1][(ni & 1) * 2 + 1];
                    asm volatile(
                        "mma.sync.aligned.m16n8k16.row.col.f32.f16.f16.f32 "
                        "{%0,%1,%2,%3}, {%4,%5,%6,%7}, {%8,%9}, {%0,%1,%2,%3};\n"
                        : "+f"(c[mi][ni][0]), "+f"(c[mi][ni][1]),
                          "+f"(c[mi][ni][2]), "+f"(c[mi][ni][3])
                        : "r"(a[mi][0]), "r"(a[mi][1]), "r"(a[mi][2]), "r"(a[mi][3]),
                          "r"(bb0), "r"(bb1));
                }
        }
        buf ^= 1;
    }

    int g = lane >> 2, q = lane & 3;
#pragma unroll
    for (int ni = 0; ni < 4; ni++) {
        int ncol = n0 + wn * 32 + ni * 8 + 2 * q;
        if (ncol >= N) continue;
        float b0 = bias[ncol], b1 = bias[ncol + 1];
#pragma unroll
        for (int mi = 0; mi < 4; mi++) {
            int r0 = m0 + wm * 64 + mi * 16 + g;
            *(float2*)(C + (size_t)r0 * N + ncol) =
                make_float2(c[mi][ni][0] + b0, c[mi][ni][1] + b1);
            *(float2*)(C + (size_t)(r0 + 8) * N + ncol) =
                make_float2(c[mi][ni][2] + b0, c[mi][ni][3] + b1);
        }
    }
#undef SOFF
}

// ---------------------------- GRU recurrence --------------------------------
// One block per (batch pair {2bx,2bx+1}, direction d).  384 threads.
// Both batches share direction d -> same Whh -> thread's w2[64] regs serve
// two independent dot-product chains (fills lockstep stall cycles).
// Role map:  warps 0-7: lanes 0-15 -> gate r of j = wid*16+lane,
//                       lanes 16-31 -> gate n of same j (r via shfl.xor 16)
//            warps 8-11: gate z of j = (wid-8)*32+lane (via smem zbuf).
__global__ void __launch_bounds__(384, 1) recur_k(
    const float* __restrict__ GI,    // [B*T][768] or [B][768] (gi_const)
    const float* __restrict__ Whh,   // [2][384][128]
    const float* __restrict__ bhh,   // [2][384]
    float* __restrict__ Yf,          // fp32 outputs [B*T][256] or nullptr
    __half* __restrict__ Yh,         // fp16 outputs or nullptr
    float* __restrict__ Hout,        // [B][512]
    int loff, int gi_const)
{
    int b0 = blockIdx.x * 2, b1 = b0 + 1, d = blockIdx.y;
    int o = threadIdx.x;
    int wid = o >> 5, lane = o & 31;

    int gate, j;
    if (wid < 8) {
        gate = (lane < 16) ? 0 : 2;
        j = wid * 16 + (lane & 15);
    } else {
        gate = 1;
        j = (wid - 8) * 32 + lane;
    }
    int row = gate * H_ + j;               // 0..383
    bool is_n = (gate == 2);

    __shared__ __align__(16) float shA[128], shB[128];
    __shared__ float zbufA[128], zbufB[128];

    unsigned long long w2[64];
    const float2* wrow = (const float2*)(Whh + ((size_t)(d * G3H + row)) * H_);
#pragma unroll
    for (int i = 0; i < 64; i++) {
        float2 v = wrow[i];
        w2[i] = pk2(v.x, v.y);
    }
    float bh = bhh[d * G3H + row];
    if (o < 128) { shA[o] = 0.f; shB[o] = 0.f; }
    __syncthreads();

    int giRow = d * G3H + row;
    float giA_next, giB_next;
    if (gi_const) {
        giA_next = GI[(size_t)b0 * 768 + giRow];
        giB_next = GI[(size_t)b1 * 768 + giRow];
    } else {
        int t0 = d ? (T_ - 1) : 0;
        giA_next = GI[((size_t)(b0 * T_ + t0)) * 768 + giRow];
        giB_next = GI[((size_t)(b1 * T_ + t0)) * 768 + giRow];
    }

    for (int s = 0; s < T_; s++) {
        int t = d ? (T_ - 1 - s) : s;
        float giA = giA_next, giB = giB_next;
        if (!gi_const && s + 1 < T_) {
            int t1 = d ? (T_ - 2 - s) : (s + 1);
            giA_next = GI[((size_t)(b0 * T_ + t1)) * 768 + giRow];
            giB_next = GI[((size_t)(b1 * T_ + t1)) * 768 + giRow];
        }

        unsigned long long a0 = pk2(bh, 0.f), a1 = 0ull;
        unsigned long long c0 = pk2(bh, 0.f), c1 = 0ull;
        const ulonglong2* hA = (const ulonglong2*)shA;
        const ulonglong2* hB = (const ulonglong2*)shB;
#pragma unroll
        for (int i = 0; i < 16; i++) {
            ulonglong2 va0 = hA[2 * i];
            ulonglong2 va1 = hA[2 * i + 1];
            ulonglong2 vb0 = hB[2 * i];
            ulonglong2 vb1 = hB[2 * i + 1];
            a0 = f2fma(w2[4 * i + 0], va0.x, a0);
            a1 = f2fma(w2[4 * i + 1], va0.y, a1);
            c0 = f2fma(w2[4 * i + 0], vb0.x, c0);
            c1 = f2fma(w2[4 * i + 1], vb0.y, c1);
            a0 = f2fma(w2[4 * i + 2], va1.x, a0);
            a1 = f2fma(w2[4 * i + 3], va1.y, a1);
            c0 = f2fma(w2[4 * i + 2], vb1.x, c0);
            c1 = f2fma(w2[4 * i + 3], vb1.y, c1);
        }
        float pa0, pa1, pa2, pa3, pb0, pb1, pb2, pb3;
        upk(a0, pa0, pa1); upk(a1, pa2, pa3);
        upk(c0, pb0, pb1); upk(c1, pb2, pb3);
        float ghA = (pa0 + pa2) + (pa1 + pa3);
        float ghB = (pb0 + pb2) + (pb1 + pb3);

        float holdA = shA[j], holdB = shB[j];

        float rvA = 0.f, rvB = 0.f;
        if (!is_n) {
            float aA = fast_sigm(giA + ghA);
            float aB = fast_sigm(giB + ghB);
            if (gate == 0) { rvA = aA; rvB = aB; }
            else           { zbufA[j] = aA; zbufB[j] = aB; }
        }
        float rxA = __shfl_xor_sync(0xffffffffu, rvA, 16);
        float rxB = __shfl_xor_sync(0xffffffffu, rvB, 16);

        __syncthreads();                     // zbuf visible; h reads done

        if (is_n) {
            float nA = fast_tanh(giA + rxA * ghA);
            float nB = fast_tanh(giB + rxB * ghB);
            float zA = zbufA[j], zB = zbufB[j];
            float hnA = (1.f - zA) * nA + zA * holdA;
            float hnB = (1.f - zB) * nB + zB * holdB;
            shA[j] = hnA;
            shB[j] = hnB;
            int idxA = (b0 * T_ + t) * 256 + d * H_ + j;
            int idxB = (b1 * T_ + t) * 256 + d * H_ + j;
            if (Yf) { Yf[idxA] = hnA; Yf[idxB] = hnB; }
            if (Yh) { Yh[idxA] = __float2half(hnA); Yh[idxB] = __float2half(hnB); }
        }
        __syncthreads();
    }
    if (is_n) {
        Hout[(size_t)b0 * 512 + loff + d * H_ + j] = shA[j];
        Hout[(size_t)b1 * 512 + loff + d * H_ + j] = shB[j];
    }
}

// -------------------------------- fc head -----------------------------------
__global__ void fc_k(const float* __restrict__ ench,
                     const float* __restrict__ dech,
                     const float* __restrict__ W,
                     const float* __restrict__ bias,
                     float* __restrict__ out)
{
    int b = blockIdx.x;
    __shared__ float feat[1024];
    int tid = threadIdx.x;
    for (int i = tid; i < 512; i += 256) {
        feat[i]       = ench[b * 512 + i];
        feat[512 + i] = dech[b * 512 + i];
    }
    __syncthreads();
    int w = tid >> 5, lane = tid & 31;
    for (int c = w; c < NCLS; c += 8) {
        float acc = 0.f;
        for (int k = lane; k < 1024; k += 32)
            acc = fmaf(feat[k], W[c * 1024 + k], acc);
#pragma unroll
        for (int off = 16; off; off >>= 1)
            acc += __shfl_down_sync(0xffffffffu, acc, off);
        if (lane == 0) out[b * NCLS + c] = acc + bias[c];
    }
}

// ------------------------------- launcher -----------------------------------
extern "C" void kernel_launch(void* const* d_in, const int* in_sizes, int n_in,
                              void* d_out, int out_size)
{
    const void*  x    = d_in[0];
    const float* emb  = (const float*)d_in[1];
    const float* eWih0 = (const float*)d_in[2];
    const float* eWhh0 = (const float*)d_in[3];
    const float* ebih0 = (const float*)d_in[4];
    const float* ebhh0 = (const float*)d_in[5];
    const float* eWih1 = (const float*)d_in[6];
    const float* eWhh1 = (const float*)d_in[7];
    const float* ebih1 = (const float*)d_in[8];
    const float* ebhh1 = (const float*)d_in[9];
    const float* dWih0 = (const float*)d_in[10];
    const float* dWhh0 = (const float*)d_in[11];
    const float* dbih0 = (const float*)d_in[12];
    const float* dbhh0 = (const float*)d_in[13];
    const float* dWih1 = (const float*)d_in[14];
    const float* dWhh1 = (const float*)d_in[15];
    const float* dbih1 = (const float*)d_in[16];
    const float* dbhh1 = (const float*)d_in[17];
    const float* fcW   = (const float*)d_in[18];
    const float* fcb   = (const float*)d_in[19];
    const float* recW  = (const float*)d_in[20];
    const float* recb  = (const float*)d_in[21];

    float* out = (float*)d_out;          // [64,20]
    float* rec = out + B_ * NCLS;        // [64,100,10000]

    float *pE, *pGI, *pGIc, *pY0, *pench, *pdech;
    __half *pRECh, *pWh;
    cudaGetSymbolAddress((void**)&pE,    g_E);
    cudaGetSymbolAddress((void**)&pGI,   g_GI);
    cudaGetSymbolAddress((void**)&pGIc,  g_GIc);
    cudaGetSymbolAddress((void**)&pY0,   g_Y0);
    cudaGetSymbolAddress((void**)&pRECh, g_RECh);
    cudaGetSymbolAddress((void**)&pWh,   g_Wh);
    cudaGetSymbolAddress((void**)&pench, g_ench);
    cudaGetSymbolAddress((void**)&pdech, g_dech);

    detect_k<<<1, 64>>>((const unsigned int*)x);
    embed_k<<<(BT * 32 + 255) / 256, 256>>>(x, emb);

    // encoder layer 0
    gemm_bt_k<<<dim3(6, 50), 256>>>(pE, eWih0, ebih0, pGI, BT, 768, 128);
    recur_k<<<dim3(B_ / 2, 2), 384>>>(pGI, eWhh0, ebhh0, pY0, nullptr, pench, 0, 0);
    // encoder layer 1 (only final hidden needed)   [6th launch -> profiled]
    gemm_bt_k<<<dim3(6, 50), 256>>>(pY0, eWih1, ebih1, pGI, BT, 768, 256);
    recur_k<<<dim3(B_ / 2, 2), 384>>>(pGI, eWhh1, ebhh1, nullptr, nullptr, pench, 256, 0);
    // decoder layer 0 (broadcast input -> gi constant per step)
    gemm_bt_k<<<dim3(6, 1), 256>>>(pench, dWih0, dbih0, pGIc, B_, 768, 512);
    recur_k<<<dim3(B_ / 2, 2), 384>>>(pGIc, dWhh0, dbhh0, pY0, nullptr, pdech, 0, 1);
    // decoder layer 1 (outputs = rec_seq, written in fp16 for the HMMA GEMM)
    gemm_bt_k<<<dim3(6, 50), 256>>>(pY0, dWih1, dbih1, pGI, BT, 768, 256);
    recur_k<<<dim3(B_ / 2, 2), 384>>>(pGI, dWhh1, dbhh1, nullptr, pRECh, pdech, 256, 0);

    // heads
    cvt_k<<<(VOCAB * 128 + 255) / 256, 256>>>(recW, pWh, VOCAB * 128);
    fc_k<<<B_, 256>>>(pench, pdech, fcW, fcb, out);
    gemm_h_k<<<dim3((VOCAB + 127) / 128, BT / 128), 256>>>(
        pRECh, pWh, recb, rec, VOCAB);
}

// round 7
// speedup vs baseline: 1.2193x; 1.2193x over previous
#include <cuda_runtime.h>
#include <cuda_fp16.h>
#include <cstdint>

// ---------------------------------------------------------------------------
// FSNet: emb -> biGRU(2 layer) encoder -> broadcast -> biGRU(2 layer) decoder
//        -> fc head (64x20)  and  reconstruction GEMM (6400x10000x256)
// GRU path fp32 (f32x2 packed FMA). Reconstruction GEMM fp16 HMMA (fp32 acc),
// 128x256 block tile, cp.async double buffering + ldmatrix.
// ---------------------------------------------------------------------------

#define B_    64
#define T_    100
#define H_    128
#define G3H   384            // 3*H
#define BT    (B_*T_)        // 6400
#define VOCAB 10000
#define NCLS  20

// ------------------------------ scratch ------------------------------------
__device__ __align__(16) float  g_E   [BT * 128];     // embedded input
__device__ __align__(16) float  g_GI  [BT * 768];     // input-gate preacts
__device__ __align__(16) float  g_GIc [B_ * 768];     // dec layer0 const gi
__device__ __align__(16) float  g_Y0  [BT * 256];     // layer0 outputs
__device__ __align__(16) __half g_RECh[BT * 256];     // rec_seq in fp16
__device__ __align__(16) __half g_Wh  [VOCAB * 256];  // rec_W in fp16
__device__ __align__(16) float  g_ench[B_ * 512];
__device__ __align__(16) float  g_dech[B_ * 512];
__device__ int g_is32;

// --------------------------- helpers ---------------------------------------
__device__ __forceinline__ unsigned long long pk2(float x, float y) {
    unsigned long long r;
    asm("mov.b64 %0, {%1, %2};" : "=l"(r)
        : "r"(__float_as_uint(x)), "r"(__float_as_uint(y)));
    return r;
}
__device__ __forceinline__ void upk(unsigned long long v, float& x, float& y) {
    unsigned int a, b;
    asm("mov.b64 {%0, %1}, %2;" : "=r"(a), "=r"(b) : "l"(v));
    x = __uint_as_float(a); y = __uint_as_float(b);
}
__device__ __forceinline__ unsigned long long f2fma(unsigned long long a,
                                                    unsigned long long b,
                                                    unsigned long long c) {
    unsigned long long d;
    asm("fma.rn.f32x2 %0, %1, %2, %3;" : "=l"(d) : "l"(a), "l"(b), "l"(c));
    return d;
}
__device__ __forceinline__ float fast_sigm(float x) {
    float e;
    asm("ex2.approx.f32 %0, %1;" : "=f"(e) : "f"(-1.4426950408889634f * x));
    float r;
    asm("rcp.approx.f32 %0, %1;" : "=f"(r) : "f"(1.0f + e));
    return r;
}
__device__ __forceinline__ float fast_tanh(float x) {
    return 2.0f * fast_sigm(2.0f * x) - 1.0f;
}
__device__ __forceinline__ uint32_t smaddr(const void* p) {
    return (uint32_t)__cvta_generic_to_shared(p);
}
__device__ __forceinline__ void cp16(uint32_t dst, const void* src) {
    asm volatile("cp.async.cg.shared.global [%0], [%1], 16;"
                 :: "r"(dst), "l"(src));
}

// ------------------------- dtype detect (int32 vs int64) --------------------
__global__ void detect_k(const unsigned int* p) {
    __shared__ int s;
    if (threadIdx.x == 0) s = 0;
    __syncthreads();
    if (p[2 * threadIdx.x + 1] != 0) atomicOr(&s, 1);
    __syncthreads();
    if (threadIdx.x == 0) g_is32 = s;
}

// ------------------------------- embedding ----------------------------------
__global__ void embed_k(const void* xraw, const float* __restrict__ emb) {
    int s = blockIdx.x * blockDim.x + threadIdx.x;
    if (s >= BT * 32) return;
    int i = s >> 5, t = s & 31;
    long long xi;
    if (g_is32) xi = ((const int*)xraw)[i];
    else        xi = ((const long long*)xraw)[i];
    int r = (int)xi;
    if (r > 9999) r = 9999;
    if (r < 0)    r = 0;
    ((float4*)g_E)[s] = ((const float4*)emb)[r * 32 + t];
}

// -------------------------- fp32 -> fp16 convert ----------------------------
__global__ void cvt_k(const float* __restrict__ src, __half* __restrict__ dst,
                      int n2) {
    int i = blockIdx.x * blockDim.x + threadIdx.x;
    if (i >= n2) return;
    float2 v = ((const float2*)src)[i];
    ((__half2*)dst)[i] = __floats2half2_rn(v.x, v.y);
}

// ------------------------------ tiled fp32 GEMM -----------------------------
// C[M,N] = A[M,K] @ B[N,K]^T + bias[N].
#define BM 128
#define BN 128
#define BKt 16

__global__ void __launch_bounds__(256) gemm_bt_k(
    const float* __restrict__ A, const float* __restrict__ Bm,
    const float* __restrict__ bias, float* __restrict__ C,
    int M, int N, int K)
{
    __shared__ __align__(16) float As[BKt][BM + 4];
    __shared__ __align__(16) float Bs[BKt][BN + 4];
    int tid = threadIdx.x;
    int tx = tid & 15, ty = tid >> 4;
    int n0 = blockIdx.x * BN, m0 = blockIdx.y * BM;

    unsigned long long acc[4][8];
#pragma unroll
    for (int i = 0; i < 4; i++)
#pragma unroll
        for (int j = 0; j < 8; j++) acc[i][j] = 0ull;

    for (int kk = 0; kk < K; kk += BKt) {
#pragma unroll
        for (int q = 0; q < 2; q++) {
            int s = tid + q * 256;
            int row = s >> 2, kq = s & 3;
            float4 va = make_float4(0.f, 0.f, 0.f, 0.f);
            int gm = m0 + row;
            if (gm < M) va = *(const float4*)(A + (size_t)gm * K + kk + kq * 4);
            As[kq * 4 + 0][row] = va.x; As[kq * 4 + 1][row] = va.y;
            As[kq * 4 + 2][row] = va.z; As[kq * 4 + 3][row] = va.w;
            float4 vb = make_float4(0.f, 0.f, 0.f, 0.f);
            int gn = n0 + row;
            if (gn < N) vb = *(const float4*)(Bm + (size_t)gn * K + kk + kq * 4);
            Bs[kq * 4 + 0][row] = vb.x; Bs[kq * 4 + 1][row] = vb.y;
            Bs[kq * 4 + 2][row] = vb.z; Bs[kq * 4 + 3][row] = vb.w;
        }
        __syncthreads();
#pragma unroll
        for (int k = 0; k < BKt; k++) {
            const unsigned long long* ap =
                (const unsigned long long*)&As[k][ty * 8];
            unsigned long long a0 = ap[0], a1 = ap[1], a2 = ap[2], a3 = ap[3];
            float4 b0 = *(const float4*)&Bs[k][tx * 8];
            float4 b1 = *(const float4*)&Bs[k][tx * 8 + 4];
            float bv[8] = {b0.x, b0.y, b0.z, b0.w, b1.x, b1.y, b1.z, b1.w};
#pragma unroll
            for (int j = 0; j < 8; j++) {
                unsigned long long bd = pk2(bv[j], bv[j]);
                acc[0][j] = f2fma(a0, bd, acc[0][j]);
                acc[1][j] = f2fma(a1, bd, acc[1][j]);
                acc[2][j] = f2fma(a2, bd, acc[2][j]);
                acc[3][j] = f2fma(a3, bd, acc[3][j]);
            }
        }
        __syncthreads();
    }

    float bvv[8];
#pragma unroll
    for (int j = 0; j < 8; j++) {
        int gc = n0 + tx * 8 + j;
        bvv[j] = (gc < N) ? bias[gc] : 0.f;
    }
    int gc0 = n0 + tx * 8;
    bool c0ok = (gc0 < N), c1ok = (gc0 + 4 < N);
#pragma unroll
    for (int ip = 0; ip < 4; ip++) {
        float lo[8], hi[8];
#pragma unroll
        for (int j = 0; j < 8; j++) {
            upk(acc[ip][j], lo[j], hi[j]);
            lo[j] += bvv[j]; hi[j] += bvv[j];
        }
        int r0 = m0 + ty * 8 + 2 * ip;
        if (r0 < M) {
            float* cp = C + (size_t)r0 * N + gc0;
            if (c0ok) *(float4*)cp       = make_float4(lo[0], lo[1], lo[2], lo[3]);
            if (c1ok) *(float4*)(cp + 4) = make_float4(lo[4], lo[5], lo[6], lo[7]);
        }
        if (r0 + 1 < M) {
            float* cp = C + (size_t)(r0 + 1) * N + gc0;
            if (c0ok) *(float4*)cp       = make_float4(hi[0], hi[1], hi[2], hi[3]);
            if (c1ok) *(float4*)(cp + 4) = make_float4(hi[4], hi[5], hi[6], hi[7]);
        }
    }
}

// ----------------------- fp16 HMMA GEMM (rec head) --------------------------
// C[M=6400,N=10000] = A[M,256] @ B[N,256]^T + bias.
// Block 128x256, K-chunk 32 double-buffered (cp.async), 8 warps 2(M)x4(N),
// warp tile 64x64, ldmatrix.x4 from XOR-swizzled smem.
__global__ void __launch_bounds__(256, 1) gemm_h_k(
    const __half* __restrict__ A, const __half* __restrict__ Bm,
    const float* __restrict__ bias, float* __restrict__ C, int N)
{
    const int K = 256;
    __shared__ __align__(16) __half Asm[2][128 * 32];   // 16 KB
    __shared__ __align__(16) __half Bsm[2][256 * 32];   // 32 KB

    int tid = threadIdx.x, lane = tid & 31, wid = tid >> 5;
    int wm = wid & 1, wn = wid >> 1;                    // 2 x 4 warps
    int m0 = blockIdx.y * 128, n0 = blockIdx.x * 256;

    float c[4][8][4];
#pragma unroll
    for (int mi = 0; mi < 4; mi++)
#pragma unroll
        for (int ni = 0; ni < 8; ni++)
#pragma unroll
            for (int r = 0; r < 4; r++) c[mi][ni][r] = 0.f;

    // A loader: thread -> row tid>>1, chunks (tid&1)*2 .. +1  (2 cp16)
    int lrA = tid >> 1;
    int lcA = (tid & 1) * 2;
    const __half* Abase = A + (size_t)(m0 + lrA) * K;
    // B loader: thread -> row tid, chunks 0..3 (4 cp16)
    int bn = n0 + tid; if (bn > N - 1) bn = N - 1;
    const __half* Bbase = Bm + (size_t)bn * K;

#define SOFF(r, ch) ((r) * 32 + (((ch) ^ ((r) & 3)) << 3))

    // prologue: k-chunk 0 -> buf 0
#pragma unroll
    for (int c2 = 0; c2 < 2; c2++) {
        int ch = lcA + c2;
        cp16(smaddr(&Asm[0][SOFF(lrA, ch)]), Abase + ch * 8);
    }
#pragma unroll
    for (int ch = 0; ch < 4; ch++)
        cp16(smaddr(&Bsm[0][SOFF(tid, ch)]), Bbase + ch * 8);
    asm volatile("cp.async.commit_group;");

    int buf = 0;
    for (int kc = 0; kc < K / 32; kc++) {
        asm volatile("cp.async.wait_group 0;");
        __syncthreads();
        if (kc + 1 < K / 32) {
            int kk = (kc + 1) * 32;
#pragma unroll
            for (int c2 = 0; c2 < 2; c2++) {
                int ch = lcA + c2;
                cp16(smaddr(&Asm[buf ^ 1][SOFF(lrA, ch)]), Abase + kk + ch * 8);
            }
#pragma unroll
            for (int ch = 0; ch < 4; ch++)
                cp16(smaddr(&Bsm[buf ^ 1][SOFF(tid, ch)]), Bbase + kk + ch * 8);
            asm volatile("cp.async.commit_group;");
        }
#pragma unroll
        for (int ks = 0; ks < 2; ks++) {
            unsigned a[4][4], b[4][4];
#pragma unroll
            for (int mi = 0; mi < 4; mi++) {
                int row = wm * 64 + mi * 16 + (lane & 15);
                int ch  = ks * 2 + (lane >> 4);
                uint32_t ad = smaddr(&Asm[buf][SOFF(row, ch)]);
                asm volatile(
                    "ldmatrix.sync.aligned.m8n8.x4.shared.b16 {%0,%1,%2,%3}, [%4];"
                    : "=r"(a[mi][0]), "=r"(a[mi][1]), "=r"(a[mi][2]), "=r"(a[mi][3])
                    : "r"(ad));
            }
#pragma unroll
            for (int nj = 0; nj < 4; nj++) {
                int row = wn * 64 + nj * 16 + (lane & 7) + (lane >> 4) * 8;
                int ch  = ks * 2 + ((lane >> 3) & 1);
                uint32_t bd = smaddr(&Bsm[buf][SOFF(row, ch)]);
                asm volatile(
                    "ldmatrix.sync.aligned.m8n8.x4.shared.b16 {%0,%1,%2,%3}, [%4];"
                    : "=r"(b[nj][0]), "=r"(b[nj][1]), "=r"(b[nj][2]), "=r"(b[nj][3])
                    : "r"(bd));
            }
#pragma unroll
            for (int mi = 0; mi < 4; mi++)
#pragma unroll
                for (int ni = 0; ni < 8; ni++) {
                    unsigned bb0 = b[ni >> 1][(ni & 1) * 2];
                    unsigned bb1 = b[ni >> 1][(ni & 1) * 2 + 1];
                    asm volatile(
                        "mma.sync.aligned.m16n8k16.row.col.f32.f16.f16.f32 "
                        "{%0,%1,%2,%3}, {%4,%5,%6,%7}, {%8,%9}, {%0,%1,%2,%3};\n"
                        : "+f"(c[mi][ni][0]), "+f"(c[mi][ni][1]),
                          "+f"(c[mi][ni][2]), "+f"(c[mi][ni][3])
                        : "r"(a[mi][0]), "r"(a[mi][1]), "r"(a[mi][2]), "r"(a[mi][3]),
                          "r"(bb0), "r"(bb1));
                }
        }
        buf ^= 1;
    }

    int g = lane >> 2, q = lane & 3;
#pragma unroll
    for (int ni = 0; ni < 8; ni++) {
        int ncol = n0 + wn * 64 + ni * 8 + 2 * q;
        if (ncol >= N) continue;               // N even; pairs never split
        float b0 = bias[ncol], b1 = bias[ncol + 1];
#pragma unroll
        for (int mi = 0; mi < 4; mi++) {
            int r0 = m0 + wm * 64 + mi * 16 + g;
            *(float2*)(C + (size_t)r0 * N + ncol) =
                make_float2(c[mi][ni][0] + b0, c[mi][ni][1] + b1);
            *(float2*)(C + (size_t)(r0 + 8) * N + ncol) =
                make_float2(c[mi][ni][2] + b0, c[mi][ni][3] + b1);
        }
    }
#undef SOFF
}

// ---------------------------- GRU recurrence --------------------------------
// One block per (batch b, direction d).  384 threads.
// Role map:  warps 0-7: lanes 0-15 -> gate r of j = wid*16+lane,
//                       lanes 16-31 -> gate n of same j (r via shfl.xor 16)
//            warps 8-11: gate z of j = (wid-8)*32+lane (via smem zbuf).
// gi for step s+1 prefetched during step s (hides the LDG).
__global__ void __launch_bounds__(384, 1) recur_k(
    const float* __restrict__ GI,    // [B*T][768] or [B][768] (gi_const)
    const float* __restrict__ Whh,   // [2][384][128]
    const float* __restrict__ bhh,   // [2][384]
    float* __restrict__ Yf,          // fp32 outputs [B*T][256] or nullptr
    __half* __restrict__ Yh,         // fp16 outputs or nullptr
    float* __restrict__ Hout,        // [B][512]
    int loff, int gi_const)
{
    int b = blockIdx.x, d = blockIdx.y;
    int o = threadIdx.x;
    int wid = o >> 5, lane = o & 31;

    int gate, j;
    if (wid < 8) {
        gate = (lane < 16) ? 0 : 2;
        j = wid * 16 + (lane & 15);
    } else {
        gate = 1;
        j = (wid - 8) * 32 + lane;
    }
    int row = gate * H_ + j;               // 0..383
    bool is_n = (gate == 2);

    __shared__ __align__(16) float sh_h[128];
    __shared__ float zbuf[128];

    unsigned long long w2[64];
    const float2* wrow = (const float2*)(Whh + ((size_t)(d * G3H + row)) * H_);
#pragma unroll
    for (int i = 0; i < 64; i++) {
        float2 v = wrow[i];
        w2[i] = pk2(v.x, v.y);
    }
    float bh = bhh[d * G3H + row];
    if (o < 128) sh_h[o] = 0.f;
    __syncthreads();

    // prefetch gi for step 0
    float gi_next;
    if (gi_const) {
        gi_next = GI[(size_t)b * 768 + d * G3H + row];
    } else {
        int t0 = d ? (T_ - 1) : 0;
        gi_next = GI[((size_t)(b * T_ + t0)) * 768 + d * G3H + row];
    }

    for (int s = 0; s < T_; s++) {
        int t = d ? (T_ - 1 - s) : s;
        float gi = gi_next;
        if (!gi_const && s + 1 < T_) {
            int t1 = d ? (T_ - 2 - s) : (s + 1);
            gi_next = GI[((size_t)(b * T_ + t1)) * 768 + d * G3H + row];
        }

        unsigned long long acc0 = pk2(bh, 0.f);
        unsigned long long acc1 = 0ull, acc2 = 0ull, acc3 = 0ull;
        const ulonglong2* h2 = (const ulonglong2*)sh_h;
#pragma unroll
        for (int i = 0; i < 16; i++) {
            ulonglong2 va = h2[2 * i];
            ulonglong2 vb = h2[2 * i + 1];
            acc0 = f2fma(w2[4 * i + 0], va.x, acc0);
            acc1 = f2fma(w2[4 * i + 1], va.y, acc1);
            acc2 = f2fma(w2[4 * i + 2], vb.x, acc2);
            acc3 = f2fma(w2[4 * i + 3], vb.y, acc3);
        }
        float p0, p1, p2, p3, p4, p5, p6, p7;
        upk(acc0, p0, p1); upk(acc1, p2, p3);
        upk(acc2, p4, p5); upk(acc3, p6, p7);
        float gh = ((p0 + p2) + (p4 + p6)) + ((p1 + p3) + (p5 + p7));

        float hold = sh_h[j];                // old h (needed by n threads)

        float rv = 0.f;
        if (!is_n) {
            float a = fast_sigm(gi + gh);
            if (gate == 0) rv = a;           // r: keep in register for shfl
            else           zbuf[j] = a;      // z: publish before barrier
        }
        float rx = __shfl_xor_sync(0xffffffffu, rv, 16);  // r -> n lanes

        __syncthreads();                     // zbuf visible; h reads done

        if (is_n) {
            float n = fast_tanh(gi + rx * gh);
            float z = zbuf[j];
            float hn = (1.f - z) * n + z * hold;
            sh_h[j] = hn;
            int idx = (b * T_ + t) * 256 + d * H_ + j;
            if (Yf) Yf[idx] = hn;
            if (Yh) Yh[idx] = __float2half(hn);
        }
        __syncthreads();
    }
    if (is_n) Hout[(size_t)b * 512 + loff + d * H_ + j] = sh_h[j];
}

// -------------------------------- fc head -----------------------------------
__global__ void fc_k(const float* __restrict__ ench,
                     const float* __restrict__ dech,
                     const float* __restrict__ W,
                     const float* __restrict__ bias,
                     float* __restrict__ out)
{
    int b = blockIdx.x;
    __shared__ float feat[1024];
    int tid = threadIdx.x;
    for (int i = tid; i < 512; i += 256) {
        feat[i]       = ench[b * 512 + i];
        feat[512 + i] = dech[b * 512 + i];
    }
    __syncthreads();
    int w = tid >> 5, lane = tid & 31;
    for (int c = w; c < NCLS; c += 8) {
        float acc = 0.f;
        for (int k = lane; k < 1024; k += 32)
            acc = fmaf(feat[k], W[c * 1024 + k], acc);
#pragma unroll
        for (int off = 16; off; off >>= 1)
            acc += __shfl_down_sync(0xffffffffu, acc, off);
        if (lane == 0) out[b * NCLS + c] = acc + bias[c];
    }
}

// ------------------------------- launcher -----------------------------------
extern "C" void kernel_launch(void* const* d_in, const int* in_sizes, int n_in,
                              void* d_out, int out_size)
{
    const void*  x    = d_in[0];
    const float* emb  = (const float*)d_in[1];
    const float* eWih0 = (const float*)d_in[2];
    const float* eWhh0 = (const float*)d_in[3];
    const float* ebih0 = (const float*)d_in[4];
    const float* ebhh0 = (const float*)d_in[5];
    const float* eWih1 = (const float*)d_in[6];
    const float* eWhh1 = (const float*)d_in[7];
    const float* ebih1 = (const float*)d_in[8];
    const float* ebhh1 = (const float*)d_in[9];
    const float* dWih0 = (const float*)d_in[10];
    const float* dWhh0 = (const float*)d_in[11];
    const float* dbih0 = (const float*)d_in[12];
    const float* dbhh0 = (const float*)d_in[13];
    const float* dWih1 = (const float*)d_in[14];
    const float* dWhh1 = (const float*)d_in[15];
    const float* dbih1 = (const float*)d_in[16];
    const float* dbhh1 = (const float*)d_in[17];
    const float* fcW   = (const float*)d_in[18];
    const float* fcb   = (const float*)d_in[19];
    const float* recW  = (const float*)d_in[20];
    const float* recb  = (const float*)d_in[21];

    float* out = (float*)d_out;          // [64,20]
    float* rec = out + B_ * NCLS;        // [64,100,10000]

    float *pE, *pGI, *pGIc, *pY0, *pench, *pdech;
    __half *pRECh, *pWh;
    cudaGetSymbolAddress((void**)&pE,    g_E);
    cudaGetSymbolAddress((void**)&pGI,   g_GI);
    cudaGetSymbolAddress((void**)&pGIc,  g_GIc);
    cudaGetSymbolAddress((void**)&pY0,   g_Y0);
    cudaGetSymbolAddress((void**)&pRECh, g_RECh);
    cudaGetSymbolAddress((void**)&pWh,   g_Wh);
    cudaGetSymbolAddress((void**)&pench, g_ench);
    cudaGetSymbolAddress((void**)&pdech, g_dech);

    detect_k<<<1, 64>>>((const unsigned int*)x);
    embed_k<<<(BT * 32 + 255) / 256, 256>>>(x, emb);

    // encoder layer 0
    gemm_bt_k<<<dim3(6, 50), 256>>>(pE, eWih0, ebih0, pGI, BT, 768, 128);
    recur_k<<<dim3(B_, 2), 384>>>(pGI, eWhh0, ebhh0, pY0, nullptr, pench, 0, 0);
    // encoder layer 1 (only final hidden needed)
    gemm_bt_k<<<dim3(6, 50), 256>>>(pY0, eWih1, ebih1, pGI, BT, 768, 256);
    recur_k<<<dim3(B_, 2), 384>>>(pGI, eWhh1, ebhh1, nullptr, nullptr, pench, 256, 0);
    // decoder layer 0 (broadcast input -> gi constant per step)
    gemm_bt_k<<<dim3(6, 1), 256>>>(pench, dWih0, dbih0, pGIc, B_, 768, 512);
    recur_k<<<dim3(B_, 2), 384>>>(pGIc, dWhh0, dbhh0, pY0, nullptr, pdech, 0, 1);
    // decoder layer 1 (outputs = rec_seq, written in fp16 for the HMMA GEMM)
    gemm_bt_k<<<dim3(6, 50), 256>>>(pY0, dWih1, dbih1, pGI, BT, 768, 256);
    recur_k<<<dim3(B_, 2), 384>>>(pGI, dWhh1, dbhh1, nullptr, pRECh, pdech, 256, 0);

    // heads
    cvt_k<<<(VOCAB * 128 + 255) / 256, 256>>>(recW, pWh, VOCAB * 128);
    fc_k<<<B_, 256>>>(pench, pdech, fcW, fcb, out);
    gemm_h_k<<<dim3((VOCAB + 255) / 256, BT / 128), 256>>>(
        pRECh, pWh, recb, rec, VOCAB);
}

// round 8
// speedup vs baseline: 1.2872x; 1.0557x over previous
#include <cuda_runtime.h>
#include <cuda_fp16.h>
#include <cstdint>

// ---------------------------------------------------------------------------
// FSNet: emb -> biGRU(2 layer) encoder -> broadcast -> biGRU(2 layer) decoder
//        -> fc head (64x20)  and  reconstruction GEMM (6400x10000x256)
// GRU path fp32 (f32x2 packed FMA); stores offloaded to idle z-warps.
// Reconstruction GEMM fp16 HMMA (fp32 acc), 128x128 tile, occ 2,
// cp.async double buffering + ldmatrix.
// ---------------------------------------------------------------------------

#define B_    64
#define T_    100
#define H_    128
#define G3H   384            // 3*H
#define BT    (B_*T_)        // 6400
#define VOCAB 10000
#define NCLS  20

// ------------------------------ scratch ------------------------------------
__device__ __align__(16) float  g_E   [BT * 128];     // embedded input
__device__ __align__(16) float  g_GI  [BT * 768];     // input-gate preacts
__device__ __align__(16) float  g_GIc [B_ * 768];     // dec layer0 const gi
__device__ __align__(16) float  g_Y0  [BT * 256];     // layer0 outputs
__device__ __align__(16) __half g_RECh[BT * 256];     // rec_seq in fp16
__device__ __align__(16) __half g_Wh  [VOCAB * 256];  // rec_W in fp16
__device__ __align__(16) float  g_ench[B_ * 512];
__device__ __align__(16) float  g_dech[B_ * 512];
__device__ int g_is32;

// --------------------------- helpers ---------------------------------------
__device__ __forceinline__ unsigned long long pk2(float x, float y) {
    unsigned long long r;
    asm("mov.b64 %0, {%1, %2};" : "=l"(r)
        : "r"(__float_as_uint(x)), "r"(__float_as_uint(y)));
    return r;
}
__device__ __forceinline__ void upk(unsigned long long v, float& x, float& y) {
    unsigned int a, b;
    asm("mov.b64 {%0, %1}, %2;" : "=r"(a), "=r"(b) : "l"(v));
    x = __uint_as_float(a); y = __uint_as_float(b);
}
__device__ __forceinline__ unsigned long long f2fma(unsigned long long a,
                                                    unsigned long long b,
                                                    unsigned long long c) {
    unsigned long long d;
    asm("fma.rn.f32x2 %0, %1, %2, %3;" : "=l"(d) : "l"(a), "l"(b), "l"(c));
    return d;
}
__device__ __forceinline__ float fast_sigm(float x) {
    float e;
    asm("ex2.approx.f32 %0, %1;" : "=f"(e) : "f"(-1.4426950408889634f * x));
    float r;
    asm("rcp.approx.f32 %0, %1;" : "=f"(r) : "f"(1.0f + e));
    return r;
}
__device__ __forceinline__ float fast_tanh(float x) {
    return 2.0f * fast_sigm(2.0f * x) - 1.0f;
}
__device__ __forceinline__ uint32_t smaddr(const void* p) {
    return (uint32_t)__cvta_generic_to_shared(p);
}
__device__ __forceinline__ void cp16(uint32_t dst, const void* src) {
    asm volatile("cp.async.cg.shared.global [%0], [%1], 16;"
                 :: "r"(dst), "l"(src));
}

// ------------------------- dtype detect (int32 vs int64) --------------------
__global__ void detect_k(const unsigned int* p) {
    __shared__ int s;
    if (threadIdx.x == 0) s = 0;
    __syncthreads();
    if (p[2 * threadIdx.x + 1] != 0) atomicOr(&s, 1);
    __syncthreads();
    if (threadIdx.x == 0) g_is32 = s;
}

// ------------------------------- embedding ----------------------------------
__global__ void embed_k(const void* xraw, const float* __restrict__ emb) {
    int s = blockIdx.x * blockDim.x + threadIdx.x;
    if (s >= BT * 32) return;
    int i = s >> 5, t = s & 31;
    long long xi;
    if (g_is32) xi = ((const int*)xraw)[i];
    else        xi = ((const long long*)xraw)[i];
    int r = (int)xi;
    if (r > 9999) r = 9999;
    if (r < 0)    r = 0;
    ((float4*)g_E)[s] = ((const float4*)emb)[r * 32 + t];
}

// -------------------------- fp32 -> fp16 convert ----------------------------
__global__ void cvt_k(const float* __restrict__ src, __half* __restrict__ dst,
                      int n2) {
    int i = blockIdx.x * blockDim.x + threadIdx.x;
    if (i >= n2) return;
    float2 v = ((const float2*)src)[i];
    ((__half2*)dst)[i] = __floats2half2_rn(v.x, v.y);
}

// ------------------------------ tiled fp32 GEMM -----------------------------
// C[M,N] = A[M,K] @ B[N,K]^T + bias[N].
#define BM 128
#define BN 128
#define BKt 16

__global__ void __launch_bounds__(256) gemm_bt_k(
    const float* __restrict__ A, const float* __restrict__ Bm,
    const float* __restrict__ bias, float* __restrict__ C,
    int M, int N, int K)
{
    __shared__ __align__(16) float As[BKt][BM + 4];
    __shared__ __align__(16) float Bs[BKt][BN + 4];
    int tid = threadIdx.x;
    int tx = tid & 15, ty = tid >> 4;
    int n0 = blockIdx.x * BN, m0 = blockIdx.y * BM;

    unsigned long long acc[4][8];
#pragma unroll
    for (int i = 0; i < 4; i++)
#pragma unroll
        for (int j = 0; j < 8; j++) acc[i][j] = 0ull;

    for (int kk = 0; kk < K; kk += BKt) {
#pragma unroll
        for (int q = 0; q < 2; q++) {
            int s = tid + q * 256;
            int row = s >> 2, kq = s & 3;
            float4 va = make_float4(0.f, 0.f, 0.f, 0.f);
            int gm = m0 + row;
            if (gm < M) va = *(const float4*)(A + (size_t)gm * K + kk + kq * 4);
            As[kq * 4 + 0][row] = va.x; As[kq * 4 + 1][row] = va.y;
            As[kq * 4 + 2][row] = va.z; As[kq * 4 + 3][row] = va.w;
            float4 vb = make_float4(0.f, 0.f, 0.f, 0.f);
            int gn = n0 + row;
            if (gn < N) vb = *(const float4*)(Bm + (size_t)gn * K + kk + kq * 4);
            Bs[kq * 4 + 0][row] = vb.x; Bs[kq * 4 + 1][row] = vb.y;
            Bs[kq * 4 + 2][row] = vb.z; Bs[kq * 4 + 3][row] = vb.w;
        }
        __syncthreads();
#pragma unroll
        for (int k = 0; k < BKt; k++) {
            const unsigned long long* ap =
                (const unsigned long long*)&As[k][ty * 8];
            unsigned long long a0 = ap[0], a1 = ap[1], a2 = ap[2], a3 = ap[3];
            float4 b0 = *(const float4*)&Bs[k][tx * 8];
            float4 b1 = *(const float4*)&Bs[k][tx * 8 + 4];
            float bv[8] = {b0.x, b0.y, b0.z, b0.w, b1.x, b1.y, b1.z, b1.w};
#pragma unroll
            for (int j = 0; j < 8; j++) {
                unsigned long long bd = pk2(bv[j], bv[j]);
                acc[0][j] = f2fma(a0, bd, acc[0][j]);
                acc[1][j] = f2fma(a1, bd, acc[1][j]);
                acc[2][j] = f2fma(a2, bd, acc[2][j]);
                acc[3][j] = f2fma(a3, bd, acc[3][j]);
            }
        }
        __syncthreads();
    }

    float bvv[8];
#pragma unroll
    for (int j = 0; j < 8; j++) {
        int gc = n0 + tx * 8 + j;
        bvv[j] = (gc < N) ? bias[gc] : 0.f;
    }
    int gc0 = n0 + tx * 8;
    bool c0ok = (gc0 < N), c1ok = (gc0 + 4 < N);
#pragma unroll
    for (int ip = 0; ip < 4; ip++) {
        float lo[8], hi[8];
#pragma unroll
        for (int j = 0; j < 8; j++) {
            upk(acc[ip][j], lo[j], hi[j]);
            lo[j] += bvv[j]; hi[j] += bvv[j];
        }
        int r0 = m0 + ty * 8 + 2 * ip;
        if (r0 < M) {
            float* cp = C + (size_t)r0 * N + gc0;
            if (c0ok) *(float4*)cp       = make_float4(lo[0], lo[1], lo[2], lo[3]);
            if (c1ok) *(float4*)(cp + 4) = make_float4(lo[4], lo[5], lo[6], lo[7]);
        }
        if (r0 + 1 < M) {
            float* cp = C + (size_t)(r0 + 1) * N + gc0;
            if (c0ok) *(float4*)cp       = make_float4(hi[0], hi[1], hi[2], hi[3]);
            if (c1ok) *(float4*)(cp + 4) = make_float4(hi[4], hi[5], hi[6], hi[7]);
        }
    }
}

// ----------------------- fp16 HMMA GEMM (rec head) --------------------------
// C[M=6400,N=10000] = A[M,256] @ B[N,256]^T + bias.
// Block tile 128x128, K-chunk 32 double-buffered (cp.async), 8 warps 2x4,
// warp tile 64x32, ldmatrix.x4 from XOR-swizzled smem.  Occupancy 2.
__global__ void __launch_bounds__(256, 2) gemm_h_k(
    const __half* __restrict__ A, const __half* __restrict__ Bm,
    const float* __restrict__ bias, float* __restrict__ C, int N)
{
    const int K = 256;
    __shared__ __align__(16) __half Asm[2][128 * 32];
    __shared__ __align__(16) __half Bsm[2][128 * 32];

    int tid = threadIdx.x, lane = tid & 31, wid = tid >> 5;
    int wm = wid & 1, wn = wid >> 1;
    int m0 = blockIdx.y * 128, n0 = blockIdx.x * 128;

    float c[4][4][4];
#pragma unroll
    for (int mi = 0; mi < 4; mi++)
#pragma unroll
        for (int ni = 0; ni < 4; ni++)
#pragma unroll
            for (int r = 0; r < 4; r++) c[mi][ni][r] = 0.f;

    int lr = tid >> 1;
    int lc0 = (tid & 1) * 2;
    int bn = n0 + lr; if (bn > N - 1) bn = N - 1;
    const __half* Abase = A + (size_t)(m0 + lr) * K;
    const __half* Bbase = Bm + (size_t)bn * K;

#define SOFF(r, ch) ((r) * 32 + (((ch) ^ ((r) & 3)) << 3))

#pragma unroll
    for (int c2 = 0; c2 < 2; c2++) {
        int ch = lc0 + c2;
        cp16(smaddr(&Asm[0][SOFF(lr, ch)]), Abase + ch * 8);
        cp16(smaddr(&Bsm[0][SOFF(lr, ch)]), Bbase + ch * 8);
    }
    asm volatile("cp.async.commit_group;");

    int buf = 0;
    for (int kc = 0; kc < K / 32; kc++) {
        asm volatile("cp.async.wait_group 0;");
        __syncthreads();
        if (kc + 1 < K / 32) {
            int kk = (kc + 1) * 32;
#pragma unroll
            for (int c2 = 0; c2 < 2; c2++) {
                int ch = lc0 + c2;
                cp16(smaddr(&Asm[buf ^ 1][SOFF(lr, ch)]), Abase + kk + ch * 8);
                cp16(smaddr(&Bsm[buf ^ 1][SOFF(lr, ch)]), Bbase + kk + ch * 8);
            }
            asm volatile("cp.async.commit_group;");
        }
#pragma unroll
        for (int ks = 0; ks < 2; ks++) {
            unsigned a[4][4], b[2][4];
#pragma unroll
            for (int mi = 0; mi < 4; mi++) {
                int row = wm * 64 + mi * 16 + (lane & 15);
                int ch  = ks * 2 + (lane >> 4);
                uint32_t ad = smaddr(&Asm[buf][SOFF(row, ch)]);
                asm volatile(
                    "ldmatrix.sync.aligned.m8n8.x4.shared.b16 {%0,%1,%2,%3}, [%4];"
                    : "=r"(a[mi][0]), "=r"(a[mi][1]), "=r"(a[mi][2]), "=r"(a[mi][3])
                    : "r"(ad));
            }
#pragma unroll
            for (int nj = 0; nj < 2; nj++) {
                int row = wn * 32 + nj * 16 + (lane & 7) + (lane >> 4) * 8;
                int ch  = ks * 2 + ((lane >> 3) & 1);
                uint32_t bd = smaddr(&Bsm[buf][SOFF(row, ch)]);
                asm volatile(
                    "ldmatrix.sync.aligned.m8n8.x4.shared.b16 {%0,%1,%2,%3}, [%4];"
                    : "=r"(b[nj][0]), "=r"(b[nj][1]), "=r"(b[nj][2]), "=r"(b[nj][3])
                    : "r"(bd));
            }
#pragma unroll
            for (int mi = 0; mi < 4; mi++)
#pragma unroll
                for (int ni = 0; ni < 4; ni++) {
                    unsigned bb0 = b[ni >> 1][(ni & 1) * 2];
                    unsigned bb1 = b[ni >> 1][(ni & 1) * 2 + 1];
                    asm volatile(
                        "mma.sync.aligned.m16n8k16.row.col.f32.f16.f16.f32 "
                        "{%0,%1,%2,%3}, {%4,%5,%6,%7}, {%8,%9}, {%0,%1,%2,%3};\n"
                        : "+f"(c[mi][ni][0]), "+f"(c[mi][ni][1]),
                          "+f"(c[mi][ni][2]), "+f"(c[mi][ni][3])
                        : "r"(a[mi][0]), "r"(a[mi][1]), "r"(a[mi][2]), "r"(a[mi][3]),
                          "r"(bb0), "r"(bb1));
                }
        }
        buf ^= 1;
    }

    int g = lane >> 2, q = lane & 3;
#pragma unroll
    for (int ni = 0; ni < 4; ni++) {
        int ncol = n0 + wn * 32 + ni * 8 + 2 * q;
        if (ncol >= N) continue;               // N even; pairs never split
        float b0 = bias[ncol], b1 = bias[ncol + 1];
#pragma unroll
        for (int mi = 0; mi < 4; mi++) {
            int r0 = m0 + wm * 64 + mi * 16 + g;
            *(float2*)(C + (size_t)r0 * N + ncol) =
                make_float2(c[mi][ni][0] + b0, c[mi][ni][1] + b1);
            *(float2*)(C + (size_t)(r0 + 8) * N + ncol) =
                make_float2(c[mi][ni][2] + b0, c[mi][ni][3] + b1);
        }
    }
#undef SOFF
}

// ---------------------------- GRU recurrence --------------------------------
// One block per (batch b, direction d).  384 threads.
// Role map:  warps 0-7: lanes 0-15 -> gate r of j = wid*16+lane,
//                       lanes 16-31 -> gate n of same j (r via shfl.xor 16)
//            warps 8-11: gate z of j = (wid-8)*32+lane (via smem zbuf).
// z-warps also flush the PREVIOUS step's h (still in smem) to gmem, taking
// all global stores off the serial n-tail.  gi prefetched one step ahead.
__global__ void __launch_bounds__(384, 1) recur_k(
    const float* __restrict__ GI,    // [B*T][768] or [B][768] (gi_const)
    const float* __restrict__ Whh,   // [2][384][128]
    const float* __restrict__ bhh,   // [2][384]
    float* __restrict__ Yf,          // fp32 outputs [B*T][256] or nullptr
    __half* __restrict__ Yh,         // fp16 outputs or nullptr
    float* __restrict__ Hout,        // [B][512]
    int loff, int gi_const)
{
    int b = blockIdx.x, d = blockIdx.y;
    int o = threadIdx.x;
    int wid = o >> 5, lane = o & 31;

    int gate, j;
    if (wid < 8) {
        gate = (lane < 16) ? 0 : 2;
        j = wid * 16 + (lane & 15);
    } else {
        gate = 1;
        j = (wid - 8) * 32 + lane;
    }
    int row = gate * H_ + j;               // 0..383
    bool is_n = (gate == 2);
    bool is_z = (gate == 1);

    __shared__ __align__(16) float sh_h[128];
    __shared__ float zbuf[128];

    unsigned long long w2[64];
    const float2* wrow = (const float2*)(Whh + ((size_t)(d * G3H + row)) * H_);
#pragma unroll
    for (int i = 0; i < 64; i++) {
        float2 v = wrow[i];
        w2[i] = pk2(v.x, v.y);
    }
    float bh = bhh[d * G3H + row];
    if (o < 128) sh_h[o] = 0.f;
    __syncthreads();

    // prefetch gi for step 0
    float gi_next;
    if (gi_const) {
        gi_next = GI[(size_t)b * 768 + d * G3H + row];
    } else {
        int t0 = d ? (T_ - 1) : 0;
        gi_next = GI[((size_t)(b * T_ + t0)) * 768 + d * G3H + row];
    }

    for (int s = 0; s < T_; s++) {
        int t = d ? (T_ - 1 - s) : s;
        float gi = gi_next;
        if (!gi_const && s + 1 < T_) {
            int t1 = d ? (T_ - 2 - s) : (s + 1);
            gi_next = GI[((size_t)(b * T_ + t1)) * 768 + d * G3H + row];
        }

        unsigned long long acc0 = pk2(bh, 0.f);
        unsigned long long acc1 = 0ull, acc2 = 0ull, acc3 = 0ull;
        const ulonglong2* h2 = (const ulonglong2*)sh_h;
#pragma unroll
        for (int i = 0; i < 16; i++) {
            ulonglong2 va = h2[2 * i];
            ulonglong2 vb = h2[2 * i + 1];
            acc0 = f2fma(w2[4 * i + 0], va.x, acc0);
            acc1 = f2fma(w2[4 * i + 1], va.y, acc1);
            acc2 = f2fma(w2[4 * i + 2], vb.x, acc2);
            acc3 = f2fma(w2[4 * i + 3], vb.y, acc3);
        }
        float p0, p1, p2, p3, p4, p5, p6, p7;
        upk(acc0, p0, p1); upk(acc1, p2, p3);
        upk(acc2, p4, p5); upk(acc3, p6, p7);
        float gh = ((p0 + p2) + (p4 + p6)) + ((p1 + p3) + (p5 + p7));

        float hold = sh_h[j];                // old h (n: update; z: flush)

        // z-warps flush the previous step's h to gmem (off the n critical path)
        if (is_z && s > 0) {
            int tp = d ? (T_ - s) : (s - 1);
            int idxp = (b * T_ + tp) * 256 + d * H_ + j;
            if (Yf) Yf[idxp] = hold;
            if (Yh) Yh[idxp] = __float2half(hold);
        }

        float rv = 0.f;
        if (!is_n) {
            float a = fast_sigm(gi + gh);
            if (gate == 0) rv = a;           // r: keep in register for shfl
            else           zbuf[j] = a;      // z: publish before barrier
        }
        float rx = __shfl_xor_sync(0xffffffffu, rv, 16);  // r -> n lanes

        __syncthreads();                     // zbuf visible; h reads done

        if (is_n) {
            float n = fast_tanh(gi + rx * gh);
            float z = zbuf[j];
            float hn = (1.f - z) * n + z * hold;
            sh_h[j] = hn;
        }
        __syncthreads();
        (void)t;
    }
    // final flush: h of last step + Hout (z-warps)
    if (is_z) {
        float hfin = sh_h[j];
        int tl = d ? 0 : (T_ - 1);
        int idxl = (b * T_ + tl) * 256 + d * H_ + j;
        if (Yf) Yf[idxl] = hfin;
        if (Yh) Yh[idxl] = __float2half(hfin);
        Hout[(size_t)b * 512 + loff + d * H_ + j] = hfin;
    }
}

// -------------------------------- fc head -----------------------------------
__global__ void fc_k(const float* __restrict__ ench,
                     const float* __restrict__ dech,
                     const float* __restrict__ W,
                     const float* __restrict__ bias,
                     float* __restrict__ out)
{
    int b = blockIdx.x;
    __shared__ float feat[1024];
    int tid = threadIdx.x;
    for (int i = tid; i < 512; i += 256) {
        feat[i]       = ench[b * 512 + i];
        feat[512 + i] = dech[b * 512 + i];
    }
    __syncthreads();
    int w = tid >> 5, lane = tid & 31;
    for (int c = w; c < NCLS; c += 8) {
        float acc = 0.f;
        for (int k = lane; k < 1024; k += 32)
            acc = fmaf(feat[k], W[c * 1024 + k], acc);
#pragma unroll
        for (int off = 16; off; off >>= 1)
            acc += __shfl_down_sync(0xffffffffu, acc, off);
        if (lane == 0) out[b * NCLS + c] = acc + bias[c];
    }
}

// ------------------------------- launcher -----------------------------------
extern "C" void kernel_launch(void* const* d_in, const int* in_sizes, int n_in,
                              void* d_out, int out_size)
{
    const void*  x    = d_in[0];
    const float* emb  = (const float*)d_in[1];
    const float* eWih0 = (const float*)d_in[2];
    const float* eWhh0 = (const float*)d_in[3];
    const float* ebih0 = (const float*)d_in[4];
    const float* ebhh0 = (const float*)d_in[5];
    const float* eWih1 = (const float*)d_in[6];
    const float* eWhh1 = (const float*)d_in[7];
    const float* ebih1 = (const float*)d_in[8];
    const float* ebhh1 = (const float*)d_in[9];
    const float* dWih0 = (const float*)d_in[10];
    const float* dWhh0 = (const float*)d_in[11];
    const float* dbih0 = (const float*)d_in[12];
    const float* dbhh0 = (const float*)d_in[13];
    const float* dWih1 = (const float*)d_in[14];
    const float* dWhh1 = (const float*)d_in[15];
    const float* dbih1 = (const float*)d_in[16];
    const float* dbhh1 = (const float*)d_in[17];
    const float* fcW   = (const float*)d_in[18];
    const float* fcb   = (const float*)d_in[19];
    const float* recW  = (const float*)d_in[20];
    const float* recb  = (const float*)d_in[21];

    float* out = (float*)d_out;          // [64,20]
    float* rec = out + B_ * NCLS;        // [64,100,10000]

    float *pE, *pGI, *pGIc, *pY0, *pench, *pdech;
    __half *pRECh, *pWh;
    cudaGetSymbolAddress((void**)&pE,    g_E);
    cudaGetSymbolAddress((void**)&pGI,   g_GI);
    cudaGetSymbolAddress((void**)&pGIc,  g_GIc);
    cudaGetSymbolAddress((void**)&pY0,   g_Y0);
    cudaGetSymbolAddress((void**)&pRECh, g_RECh);
    cudaGetSymbolAddress((void**)&pWh,   g_Wh);
    cudaGetSymbolAddress((void**)&pench, g_ench);
    cudaGetSymbolAddress((void**)&pdech, g_dech);

    detect_k<<<1, 64>>>((const unsigned int*)x);
    embed_k<<<(BT * 32 + 255) / 256, 256>>>(x, emb);

    // encoder layer 0
    gemm_bt_k<<<dim3(6, 50), 256>>>(pE, eWih0, ebih0, pGI, BT, 768, 128);
    recur_k<<<dim3(B_, 2), 384>>>(pGI, eWhh0, ebhh0, pY0, nullptr, pench, 0, 0);
    // encoder layer 1 (only final hidden needed)
    gemm_bt_k<<<dim3(6, 50), 256>>>(pY0, eWih1, ebih1, pGI, BT, 768, 256);
    recur_k<<<dim3(B_, 2), 384>>>(pGI, eWhh1, ebhh1, nullptr, nullptr, pench, 256, 0);
    // decoder layer 0 (broadcast input -> gi constant per step)
    gemm_bt_k<<<dim3(6, 1), 256>>>(pench, dWih0, dbih0, pGIc, B_, 768, 512);
    recur_k<<<dim3(B_, 2), 384>>>(pGIc, dWhh0, dbhh0, pY0, nullptr, pdech, 0, 1);
    // decoder layer 1 (outputs = rec_seq, written in fp16 for the HMMA GEMM)
    gemm_bt_k<<<dim3(6, 50), 256>>>(pY0, dWih1, dbih1, pGI, BT, 768, 256);
    recur_k<<<dim3(B_, 2), 384>>>(pGI, dWhh1, dbhh1, nullptr, pRECh, pdech, 256, 0);

    // heads
    cvt_k<<<(VOCAB * 128 + 255) / 256, 256>>>(recW, pWh, VOCAB * 128);
    fc_k<<<B_, 256>>>(pench, pdech, fcW, fcb, out);
    gemm_h_k<<<dim3((VOCAB + 127) / 128, BT / 128), 256>>>(
        pRECh, pWh, recb, rec, VOCAB);
}

// round 11
// speedup vs baseline: 1.3205x; 1.0258x over previous
#include <cuda_runtime.h>
#include <cuda_fp16.h>
#include <cstdint>

// ---------------------------------------------------------------------------
// FSNet: emb -> biGRU(2 layer) encoder -> broadcast -> biGRU(2 layer) decoder
//        -> fc head (64x20)  and  reconstruction GEMM (6400x10000x256)
// GRU recurrence: split-K over warps (kills smem broadcast traffic).
// Reconstruction GEMM fp16 HMMA (fp32 acc), 128x128 tile, occ 2.
// ---------------------------------------------------------------------------

#define B_    64
#define T_    100
#define H_    128
#define G3H   384            // 3*H
#define BT    (B_*T_)        // 6400
#define VOCAB 10000
#define NCLS  20

// ------------------------------ scratch ------------------------------------
__device__ __align__(16) float  g_E   [BT * 128];     // embedded input
__device__ __align__(16) float  g_GI  [BT * 768];     // input-gate preacts
__device__ __align__(16) float  g_GIc [B_ * 768];     // dec layer0 const gi
__device__ __align__(16) float  g_Y0  [BT * 256];     // layer0 outputs
__device__ __align__(16) __half g_RECh[BT * 256];     // rec_seq in fp16
__device__ __align__(16) __half g_Wh  [VOCAB * 256];  // rec_W in fp16
__device__ __align__(16) float  g_ench[B_ * 512];
__device__ __align__(16) float  g_dech[B_ * 512];
__device__ int g_is32;

// --------------------------- helpers ---------------------------------------
__device__ __forceinline__ unsigned long long pk2(float x, float y) {
    unsigned long long r;
    asm("mov.b64 %0, {%1, %2};" : "=l"(r)
        : "r"(__float_as_uint(x)), "r"(__float_as_uint(y)));
    return r;
}
__device__ __forceinline__ void upk(unsigned long long v, float& x, float& y) {
    unsigned int a, b;
    asm("mov.b64 {%0, %1}, %2;" : "=r"(a), "=r"(b) : "l"(v));
    x = __uint_as_float(a); y = __uint_as_float(b);
}
__device__ __forceinline__ unsigned long long f2fma(unsigned long long a,
                                                    unsigned long long b,
                                                    unsigned long long c) {
    unsigned long long d;
    asm("fma.rn.f32x2 %0, %1, %2, %3;" : "=l"(d) : "l"(a), "l"(b), "l"(c));
    return d;
}
__device__ __forceinline__ float fast_sigm(float x) {
    float e;
    asm("ex2.approx.f32 %0, %1;" : "=f"(e) : "f"(-1.4426950408889634f * x));
    float r;
    asm("rcp.approx.f32 %0, %1;" : "=f"(r) : "f"(1.0f + e));
    return r;
}
__device__ __forceinline__ float fast_tanh(float x) {
    return 2.0f * fast_sigm(2.0f * x) - 1.0f;
}
__device__ __forceinline__ uint32_t smaddr(const void* p) {
    return (uint32_t)__cvta_generic_to_shared(p);
}
__device__ __forceinline__ void cp16(uint32_t dst, const void* src) {
    asm volatile("cp.async.cg.shared.global [%0], [%1], 16;"
                 :: "r"(dst), "l"(src));
}

// ------------------------- dtype detect (int32 vs int64) --------------------
__global__ void detect_k(const unsigned int* p) {
    __shared__ int s;
    if (threadIdx.x == 0) s = 0;
    __syncthreads();
    if (p[2 * threadIdx.x + 1] != 0) atomicOr(&s, 1);
    __syncthreads();
    if (threadIdx.x == 0) g_is32 = s;
}

// ------------------------------- embedding ----------------------------------
__global__ void embed_k(const void* xraw, const float* __restrict__ emb) {
    int s = blockIdx.x * blockDim.x + threadIdx.x;
    if (s >= BT * 32) return;
    int i = s >> 5, t = s & 31;
    long long xi;
    if (g_is32) xi = ((const int*)xraw)[i];
    else        xi = ((const long long*)xraw)[i];
    int r = (int)xi;
    if (r > 9999) r = 9999;
    if (r < 0)    r = 0;
    ((float4*)g_E)[s] = ((const float4*)emb)[r * 32 + t];
}

// -------------------------- fp32 -> fp16 convert ----------------------------
__global__ void cvt_k(const float* __restrict__ src, __half* __restrict__ dst,
                      int n2) {
    int i = blockIdx.x * blockDim.x + threadIdx.x;
    if (i >= n2) return;
    float2 v = ((const float2*)src)[i];
    ((__half2*)dst)[i] = __floats2half2_rn(v.x, v.y);
}

// ------------------------------ tiled fp32 GEMM -----------------------------
// C[M,N] = A[M,K] @ B[N,K]^T + bias[N].
#define BM 128
#define BN 128
#define BKt 16

__global__ void __launch_bounds__(256) gemm_bt_k(
    const float* __restrict__ A, const float* __restrict__ Bm,
    const float* __restrict__ bias, float* __restrict__ C,
    int M, int N, int K)
{
    __shared__ __align__(16) float As[BKt][BM + 4];
    __shared__ __align__(16) float Bs[BKt][BN + 4];
    int tid = threadIdx.x;
    int tx = tid & 15, ty = tid >> 4;
    int n0 = blockIdx.x * BN, m0 = blockIdx.y * BM;

    unsigned long long acc[4][8];
#pragma unroll
    for (int i = 0; i < 4; i++)
#pragma unroll
        for (int j = 0; j < 8; j++) acc[i][j] = 0ull;

    for (int kk = 0; kk < K; kk += BKt) {
#pragma unroll
        for (int q = 0; q < 2; q++) {
            int s = tid + q * 256;
            int row = s >> 2, kq = s & 3;
            float4 va = make_float4(0.f, 0.f, 0.f, 0.f);
            int gm = m0 + row;
            if (gm < M) va = *(const float4*)(A + (size_t)gm * K + kk + kq * 4);
            As[kq * 4 + 0][row] = va.x; As[kq * 4 + 1][row] = va.y;
            As[kq * 4 + 2][row] = va.z; As[kq * 4 + 3][row] = va.w;
            float4 vb = make_float4(0.f, 0.f, 0.f, 0.f);
            int gn = n0 + row;
            if (gn < N) vb = *(const float4*)(Bm + (size_t)gn * K + kk + kq * 4);
            Bs[kq * 4 + 0][row] = vb.x; Bs[kq * 4 + 1][row] = vb.y;
            Bs[kq * 4 + 2][row] = vb.z; Bs[kq * 4 + 3][row] = vb.w;
        }
        __syncthreads();
#pragma unroll
        for (int k = 0; k < BKt; k++) {
            const unsigned long long* ap =
                (const unsigned long long*)&As[k][ty * 8];
            unsigned long long a0 = ap[0], a1 = ap[1], a2 = ap[2], a3 = ap[3];
            float4 b0 = *(const float4*)&Bs[k][tx * 8];
            float4 b1 = *(const float4*)&Bs[k][tx * 8 + 4];
            float bv[8] = {b0.x, b0.y, b0.z, b0.w, b1.x, b1.y, b1.z, b1.w};
#pragma unroll
            for (int j = 0; j < 8; j++) {
                unsigned long long bd = pk2(bv[j], bv[j]);
                acc[0][j] = f2fma(a0, bd, acc[0][j]);
                acc[1][j] = f2fma(a1, bd, acc[1][j]);
                acc[2][j] = f2fma(a2, bd, acc[2][j]);
                acc[3][j] = f2fma(a3, bd, acc[3][j]);
            }
        }
        __syncthreads();
    }

    float bvv[8];
#pragma unroll
    for (int j = 0; j < 8; j++) {
        int gc = n0 + tx * 8 + j;
        bvv[j] = (gc < N) ? bias[gc] : 0.f;
    }
    int gc0 = n0 + tx * 8;
    bool c0ok = (gc0 < N), c1ok = (gc0 + 4 < N);
#pragma unroll
    for (int ip = 0; ip < 4; ip++) {
        float lo[8], hi[8];
#pragma unroll
        for (int j = 0; j < 8; j++) {
            upk(acc[ip][j], lo[j], hi[j]);
            lo[j] += bvv[j]; hi[j] += bvv[j];
        }
        int r0 = m0 + ty * 8 + 2 * ip;
        if (r0 < M) {
            float* cp = C + (size_t)r0 * N + gc0;
            if (c0ok) *(float4*)cp       = make_float4(lo[0], lo[1], lo[2], lo[3]);
            if (c1ok) *(float4*)(cp + 4) = make_float4(lo[4], lo[5], lo[6], lo[7]);
        }
        if (r0 + 1 < M) {
            float* cp = C + (size_t)(r0 + 1) * N + gc0;
            if (c0ok) *(float4*)cp       = make_float4(hi[0], hi[1], hi[2], hi[3]);
            if (c1ok) *(float4*)(cp + 4) = make_float4(hi[4], hi[5], hi[6], hi[7]);
        }
    }
}

// ----------------------- fp16 HMMA GEMM (rec head) --------------------------
// Block tile 128x128, K-chunk 32 double-buffered (cp.async), 8 warps 2x4,
// warp tile 64x32, ldmatrix.x4 from XOR-swizzled smem.  Occupancy 2.
__global__ void __launch_bounds__(256, 2) gemm_h_k(
    const __half* __restrict__ A, const __half* __restrict__ Bm,
    const float* __restrict__ bias, float* __restrict__ C, int N)
{
    const int K = 256;
    __shared__ __align__(16) __half Asm[2][128 * 32];
    __shared__ __align__(16) __half Bsm[2][128 * 32];

    int tid = threadIdx.x, lane = tid & 31, wid = tid >> 5;
    int wm = wid & 1, wn = wid >> 1;
    int m0 = blockIdx.y * 128, n0 = blockIdx.x * 128;

    float c[4][4][4];
#pragma unroll
    for (int mi = 0; mi < 4; mi++)
#pragma unroll
        for (int ni = 0; ni < 4; ni++)
#pragma unroll
            for (int r = 0; r < 4; r++) c[mi][ni][r] = 0.f;

    int lr = tid >> 1;
    int lc0 = (tid & 1) * 2;
    int bn = n0 + lr; if (bn > N - 1) bn = N - 1;
    const __half* Abase = A + (size_t)(m0 + lr) * K;
    const __half* Bbase = Bm + (size_t)bn * K;

#define SOFF(r, ch) ((r) * 32 + (((ch) ^ ((r) & 3)) << 3))

#pragma unroll
    for (int c2 = 0; c2 < 2; c2++) {
        int ch = lc0 + c2;
        cp16(smaddr(&Asm[0][SOFF(lr, ch)]), Abase + ch * 8);
        cp16(smaddr(&Bsm[0][SOFF(lr, ch)]), Bbase + ch * 8);
    }
    asm volatile("cp.async.commit_group;");

    int buf = 0;
    for (int kc = 0; kc < K / 32; kc++) {
        asm volatile("cp.async.wait_group 0;");
        __syncthreads();
        if (kc + 1 < K / 32) {
            int kk = (kc + 1) * 32;
#pragma unroll
            for (int c2 = 0; c2 < 2; c2++) {
                int ch = lc0 + c2;
                cp16(smaddr(&Asm[buf ^ 1][SOFF(lr, ch)]), Abase + kk + ch * 8);
                cp16(smaddr(&Bsm[buf ^ 1][SOFF(lr, ch)]), Bbase + kk + ch * 8);
            }
            asm volatile("cp.async.commit_group;");
        }
#pragma unroll
        for (int ks = 0; ks < 2; ks++) {
            unsigned a[4][4], b[2][4];
#pragma unroll
            for (int mi = 0; mi < 4; mi++) {
                int row = wm * 64 + mi * 16 + (lane & 15);
                int ch  = ks * 2 + (lane >> 4);
                uint32_t ad = smaddr(&Asm[buf][SOFF(row, ch)]);
                asm volatile(
                    "ldmatrix.sync.aligned.m8n8.x4.shared.b16 {%0,%1,%2,%3}, [%4];"
                    : "=r"(a[mi][0]), "=r"(a[mi][1]), "=r"(a[mi][2]), "=r"(a[mi][3])
                    : "r"(ad));
            }
#pragma unroll
            for (int nj = 0; nj < 2; nj++) {
                int row = wn * 32 + nj * 16 + (lane & 7) + (lane >> 4) * 8;
                int ch  = ks * 2 + ((lane >> 3) & 1);
                uint32_t bd = smaddr(&Bsm[buf][SOFF(row, ch)]);
                asm volatile(
                    "ldmatrix.sync.aligned.m8n8.x4.shared.b16 {%0,%1,%2,%3}, [%4];"
                    : "=r"(b[nj][0]), "=r"(b[nj][1]), "=r"(b[nj][2]), "=r"(b[nj][3])
                    : "r"(bd));
            }
#pragma unroll
            for (int mi = 0; mi < 4; mi++)
#pragma unroll
                for (int ni = 0; ni < 4; ni++) {
                    unsigned bb0 = b[ni >> 1][(ni & 1) * 2];
                    unsigned bb1 = b[ni >> 1][(ni & 1) * 2 + 1];
                    asm volatile(
                        "mma.sync.aligned.m16n8k16.row.col.f32.f16.f16.f32 "
                        "{%0,%1,%2,%3}, {%4,%5,%6,%7}, {%8,%9}, {%0,%1,%2,%3};\n"
                        : "+f"(c[mi][ni][0]), "+f"(c[mi][ni][1]),
                          "+f"(c[mi][ni][2]), "+f"(c[mi][ni][3])
                        : "r"(a[mi][0]), "r"(a[mi][1]), "r"(a[mi][2]), "r"(a[mi][3]),
                          "r"(bb0), "r"(bb1));
                }
        }
        buf ^= 1;
    }

    int g = lane >> 2, q = lane & 3;
#pragma unroll
    for (int ni = 0; ni < 4; ni++) {
        int ncol = n0 + wn * 32 + ni * 8 + 2 * q;
        if (ncol >= N) continue;
        float b0 = bias[ncol], b1 = bias[ncol + 1];
#pragma unroll
        for (int mi = 0; mi < 4; mi++) {
            int r0 = m0 + wm * 64 + mi * 16 + g;
            *(float2*)(C + (size_t)r0 * N + ncol) =
                make_float2(c[mi][ni][0] + b0, c[mi][ni][1] + b1);
            *(float2*)(C + (size_t)(r0 + 8) * N + ncol) =
                make_float2(c[mi][ni][2] + b0, c[mi][ni][3] + b1);
        }
    }
#undef SOFF
}

// ---------------------------- GRU recurrence --------------------------------
// Split-K: warp w = (output block g = w>>2 covering rows [128g,128g+128),
//                   chunk c = w&3 covering h elems [32c, 32c+32)).
// Phase 1: each thread 4 outputs x 32 elems (64 f2fma) reading only its
// 32-float chunk (8 LDS.128 bcast vs 32 before -> 4x less crossbar traffic).
// Partials to smem part[4][384] (coalesced).
// Phase 2 (warps 0-7): lanes 0-15 compute gate r of j=w*16+lane; lanes 16-31
// compute z AND n of same j (r arrives via shfl.xor 16).  2 barriers/step.
__global__ void __launch_bounds__(384, 1) recur_k(
    const float* __restrict__ GI,    // [B*T][768] or [B][768] (gi_const)
    const float* __restrict__ Whh,   // [2][384][128]
    const float* __restrict__ bhh,   // [2][384]
    float* __restrict__ Yf,          // fp32 outputs [B*T][256] or nullptr
    __half* __restrict__ Yh,         // fp16 outputs or nullptr
    float* __restrict__ Hout,        // [B][512]
    int loff, int gi_const)
{
    int b = blockIdx.x, d = blockIdx.y;
    int o = threadIdx.x;
    int w = o >> 5, l = o & 31;
    int g = w >> 2, c = w & 3;

    __shared__ __align__(16) float sh_h[128];
    __shared__ float part[4][384];

    // phase-1 weights: outputs 128g + 32k + l, elems [32c, 32c+32)
    unsigned long long w2[4][16];
#pragma unroll
    for (int k = 0; k < 4; k++) {
        int row = d * G3H + 128 * g + 32 * k + l;
        const float2* wr = (const float2*)(Whh + (size_t)row * H_) + 16 * c;
#pragma unroll
        for (int e = 0; e < 16; e++) {
            float2 v = wr[e];
            w2[k][e] = pk2(v.x, v.y);
        }
    }

    bool p2  = (w < 8);
    bool isn = p2 && (l >= 16);
    int  j2  = w * 16 + (l & 15);          // valid when p2
    int rowR = d * G3H + j2;
    int rowZ = rowR + 128;
    int rowN = rowR + 256;

    float bhR = 0.f, bhZ = 0.f, bhN = 0.f;
    if (p2) {
        if (!isn) bhR = bhh[rowR];
        else { bhZ = bhh[rowZ]; bhN = bhh[rowN]; }
    }

    if (o < 128) sh_h[o] = 0.f;
    __syncthreads();

    // prefetch gi for step 0
    float giR = 0.f, giZ = 0.f, giN = 0.f;
    if (p2) {
        size_t base;
        if (gi_const) base = (size_t)b * 768;
        else { int t0 = d ? (T_ - 1) : 0; base = (size_t)(b * T_ + t0) * 768; }
        if (!isn) giR = GI[base + rowR];
        else { giZ = GI[base + rowZ]; giN = GI[base + rowN]; }
    }

    for (int s = 0; s < T_; s++) {
        int t = d ? (T_ - 1 - s) : s;
        float gR = giR, gZ = giZ, gN = giN;
        if (p2 && !gi_const && s + 1 < T_) {
            int t1 = d ? (T_ - 2 - s) : (s + 1);
            size_t base = (size_t)(b * T_ + t1) * 768;
            if (!isn) giR = GI[base + rowR];
            else { giZ = GI[base + rowZ]; giN = GI[base + rowN]; }
        }

        // ---- phase 1: partial dot over this warp's 32-elem chunk ----
        const ulonglong2* hc = (const ulonglong2*)(sh_h + 32 * c);
        unsigned long long a0 = 0ull, a1 = 0ull, a2 = 0ull, a3 = 0ull;
#pragma unroll
        for (int q = 0; q < 8; q++) {
            ulonglong2 v = hc[q];
            a0 = f2fma(w2[0][2 * q], v.x, a0);
            a1 = f2fma(w2[1][2 * q], v.x, a1);
            a2 = f2fma(w2[2][2 * q], v.x, a2);
            a3 = f2fma(w2[3][2 * q], v.x, a3);
            a0 = f2fma(w2[0][2 * q + 1], v.y, a0);
            a1 = f2fma(w2[1][2 * q + 1], v.y, a1);
            a2 = f2fma(w2[2][2 * q + 1], v.y, a2);
            a3 = f2fma(w2[3][2 * q + 1], v.y, a3);
        }
        float x, y;
        upk(a0, x, y); part[c][128 * g + l]      = x + y;
        upk(a1, x, y); part[c][128 * g + 32 + l] = x + y;
        upk(a2, x, y); part[c][128 * g + 64 + l] = x + y;
        upk(a3, x, y); part[c][128 * g + 96 + l] = x + y;
        __syncthreads();                      // A: partials visible

        // ---- phase 2: gate math (warps 0-7 only) ----
        if (p2) {
            float rv = 0.f;
            if (!isn) {
                float sr = part[0][j2] + part[1][j2] + part[2][j2] + part[3][j2];
                rv = fast_sigm(gR + sr + bhR);
            }
            float rx = __shfl_xor_sync(0xffffffffu, rv, 16);
            if (isn) {
                int oz = 128 + j2, on = 256 + j2;
                float sz = part[0][oz] + part[1][oz] + part[2][oz] + part[3][oz];
                float sn = part[0][on] + part[1][on] + part[2][on] + part[3][on];
                float z = fast_sigm(gZ + sz + bhZ);
                float n = fast_tanh(gN + rx * (sn + bhN));
                float hold = sh_h[j2];
                float hn = (1.f - z) * n + z * hold;
                sh_h[j2] = hn;
                int idx = (b * T_ + t) * 256 + d * H_ + j2;
                if (Yf) Yf[idx] = hn;
                if (Yh) Yh[idx] = __float2half(hn);
            }
        }
        __syncthreads();                      // C: new h visible
    }
    if (isn) Hout[(size_t)b * 512 + loff + d * H_ + j2] = sh_h[j2];
}

// -------------------------------- fc head -----------------------------------
__global__ void fc_k(const float* __restrict__ ench,
                     const float* __restrict__ dech,
                     const float* __restrict__ W,
                     const float* __restrict__ bias,
                     float* __restrict__ out)
{
    int b = blockIdx.x;
    __shared__ float feat[1024];
    int tid = threadIdx.x;
    for (int i = tid; i < 512; i += 256) {
        feat[i]       = ench[b * 512 + i];
        feat[512 + i] = dech[b * 512 + i];
    }
    __syncthreads();
    int w = tid >> 5, lane = tid & 31;
    for (int c = w; c < NCLS; c += 8) {
        float acc = 0.f;
        for (int k = lane; k < 1024; k += 32)
            acc = fmaf(feat[k], W[c * 1024 + k], acc);
#pragma unroll
        for (int off = 16; off; off >>= 1)
            acc += __shfl_down_sync(0xffffffffu, acc, off);
        if (lane == 0) out[b * NCLS + c] = acc + bias[c];
    }
}

// ------------------------------- launcher -----------------------------------
extern "C" void kernel_launch(void* const* d_in, const int* in_sizes, int n_in,
                              void* d_out, int out_size)
{
    const void*  x    = d_in[0];
    const float* emb  = (const float*)d_in[1];
    const float* eWih0 = (const float*)d_in[2];
    const float* eWhh0 = (const float*)d_in[3];
    const float* ebih0 = (const float*)d_in[4];
    const float* ebhh0 = (const float*)d_in[5];
    const float* eWih1 = (const float*)d_in[6];
    const float* eWhh1 = (const float*)d_in[7];
    const float* ebih1 = (const float*)d_in[8];
    const float* ebhh1 = (const float*)d_in[9];
    const float* dWih0 = (const float*)d_in[10];
    const float* dWhh0 = (const float*)d_in[11];
    const float* dbih0 = (const float*)d_in[12];
    const float* dbhh0 = (const float*)d_in[13];
    const float* dWih1 = (const float*)d_in[14];
    const float* dWhh1 = (const float*)d_in[15];
    const float* dbih1 = (const float*)d_in[16];
    const float* dbhh1 = (const float*)d_in[17];
    const float* fcW   = (const float*)d_in[18];
    const float* fcb   = (const float*)d_in[19];
    const float* recW  = (const float*)d_in[20];
    const float* recb  = (const float*)d_in[21];

    float* out = (float*)d_out;          // [64,20]
    float* rec = out + B_ * NCLS;        // [64,100,10000]

    float *pE, *pGI, *pGIc, *pY0, *pench, *pdech;
    __half *pRECh, *pWh;
    cudaGetSymbolAddress((void**)&pE,    g_E);
    cudaGetSymbolAddress((void**)&pGI,   g_GI);
    cudaGetSymbolAddress((void**)&pGIc,  g_GIc);
    cudaGetSymbolAddress((void**)&pY0,   g_Y0);
    cudaGetSymbolAddress((void**)&pRECh, g_RECh);
    cudaGetSymbolAddress((void**)&pWh,   g_Wh);
    cudaGetSymbolAddress((void**)&pench, g_ench);
    cudaGetSymbolAddress((void**)&pdech, g_dech);

    detect_k<<<1, 64>>>((const unsigned int*)x);
    embed_k<<<(BT * 32 + 255) / 256, 256>>>(x, emb);

    // encoder layer 0
    gemm_bt_k<<<dim3(6, 50), 256>>>(pE, eWih0, ebih0, pGI, BT, 768, 128);
    recur_k<<<dim3(B_, 2), 384>>>(pGI, eWhh0, ebhh0, pY0, nullptr, pench, 0, 0);
    // encoder layer 1 (only final hidden needed)   [6th launch -> profiled]
    gemm_bt_k<<<dim3(6, 50), 256>>>(pY0, eWih1, ebih1, pGI, BT, 768, 256);
    recur_k<<<dim3(B_, 2), 384>>>(pGI, eWhh1, ebhh1, nullptr, nullptr, pench, 256, 0);
    // decoder layer 0 (broadcast input -> gi constant per step)
    gemm_bt_k<<<dim3(6, 1), 256>>>(pench, dWih0, dbih0, pGIc, B_, 768, 512);
    recur_k<<<dim3(B_, 2), 384>>>(pGIc, dWhh0, dbhh0, pY0, nullptr, pdech, 0, 1);
    // decoder layer 1 (outputs = rec_seq, written in fp16 for the HMMA GEMM)
    gemm_bt_k<<<dim3(6, 50), 256>>>(pY0, dWih1, dbih1, pGI, BT, 768, 256);
    recur_k<<<dim3(B_, 2), 384>>>(pGI, dWhh1, dbhh1, nullptr, pRECh, pdech, 256, 0);

    // heads
    cvt_k<<<(VOCAB * 128 + 255) / 256, 256>>>(recW, pWh, VOCAB * 128);
    fc_k<<<B_, 256>>>(pench, pdech, fcW, fcb, out);
    gemm_h_k<<<dim3((VOCAB + 127) / 128, BT / 128), 256>>>(
        pRECh, pWh, recb, rec, VOCAB);
}

// round 12
// speedup vs baseline: 1.3626x; 1.0319x over previous
#include <cuda_runtime.h>
#include <cuda_fp16.h>
#include <cstdint>

// ---------------------------------------------------------------------------
// FSNet: emb -> biGRU(2 layer) encoder -> broadcast -> biGRU(2 layer) decoder
//        -> fc head (64x20)  and  reconstruction GEMM (6400x10000x256)
// GRU recurrence: split-K over warps.  Reconstruction GEMM fp16 HMMA
// (fp32 acc), 128x128 tile, occ 2, conflict-free ldmatrix swizzle.
// ---------------------------------------------------------------------------

#define B_    64
#define T_    100
#define H_    128
#define G3H   384            // 3*H
#define BT    (B_*T_)        // 6400
#define VOCAB 10000
#define NCLS  20

// ------------------------------ scratch ------------------------------------
__device__ __align__(16) float  g_E   [BT * 128];     // embedded input
__device__ __align__(16) float  g_GI  [BT * 768];     // input-gate preacts
__device__ __align__(16) float  g_GIc [B_ * 768];     // dec layer0 const gi
__device__ __align__(16) float  g_Y0  [BT * 256];     // layer0 outputs
__device__ __align__(16) __half g_RECh[BT * 256];     // rec_seq in fp16
__device__ __align__(16) __half g_Wh  [VOCAB * 256];  // rec_W in fp16
__device__ __align__(16) float  g_ench[B_ * 512];
__device__ __align__(16) float  g_dech[B_ * 512];
__device__ int g_is32;

// --------------------------- helpers ---------------------------------------
__device__ __forceinline__ unsigned long long pk2(float x, float y) {
    unsigned long long r;
    asm("mov.b64 %0, {%1, %2};" : "=l"(r)
        : "r"(__float_as_uint(x)), "r"(__float_as_uint(y)));
    return r;
}
__device__ __forceinline__ void upk(unsigned long long v, float& x, float& y) {
    unsigned int a, b;
    asm("mov.b64 {%0, %1}, %2;" : "=r"(a), "=r"(b) : "l"(v));
    x = __uint_as_float(a); y = __uint_as_float(b);
}
__device__ __forceinline__ unsigned long long f2fma(unsigned long long a,
                                                    unsigned long long b,
                                                    unsigned long long c) {
    unsigned long long d;
    asm("fma.rn.f32x2 %0, %1, %2, %3;" : "=l"(d) : "l"(a), "l"(b), "l"(c));
    return d;
}
__device__ __forceinline__ float fast_sigm(float x) {
    float e;
    asm("ex2.approx.f32 %0, %1;" : "=f"(e) : "f"(-1.4426950408889634f * x));
    float r;
    asm("rcp.approx.f32 %0, %1;" : "=f"(r) : "f"(1.0f + e));
    return r;
}
__device__ __forceinline__ float fast_tanh(float x) {
    return 2.0f * fast_sigm(2.0f * x) - 1.0f;
}
__device__ __forceinline__ uint32_t smaddr(const void* p) {
    return (uint32_t)__cvta_generic_to_shared(p);
}
__device__ __forceinline__ void cp16(uint32_t dst, const void* src) {
    asm volatile("cp.async.cg.shared.global [%0], [%1], 16;"
                 :: "r"(dst), "l"(src));
}

// ------------------------- dtype detect (int32 vs int64) --------------------
__global__ void detect_k(const unsigned int* p) {
    __shared__ int s;
    if (threadIdx.x == 0) s = 0;
    __syncthreads();
    if (p[2 * threadIdx.x + 1] != 0) atomicOr(&s, 1);
    __syncthreads();
    if (threadIdx.x == 0) g_is32 = s;
}

// ------------------------------- embedding ----------------------------------
__global__ void embed_k(const void* xraw, const float* __restrict__ emb) {
    int s = blockIdx.x * blockDim.x + threadIdx.x;
    if (s >= BT * 32) return;
    int i = s >> 5, t = s & 31;
    long long xi;
    if (g_is32) xi = ((const int*)xraw)[i];
    else        xi = ((const long long*)xraw)[i];
    int r = (int)xi;
    if (r > 9999) r = 9999;
    if (r < 0)    r = 0;
    ((float4*)g_E)[s] = ((const float4*)emb)[r * 32 + t];
}

// -------------------------- fp32 -> fp16 convert ----------------------------
__global__ void cvt_k(const float* __restrict__ src, __half* __restrict__ dst,
                      int n2) {
    int i = blockIdx.x * blockDim.x + threadIdx.x;
    if (i >= n2) return;
    float2 v = ((const float2*)src)[i];
    ((__half2*)dst)[i] = __floats2half2_rn(v.x, v.y);
}

// ------------------------------ tiled fp32 GEMM -----------------------------
// C[M,N] = A[M,K] @ B[N,K]^T + bias[N].
#define BM 128
#define BN 128
#define BKt 16

__global__ void __launch_bounds__(256) gemm_bt_k(
    const float* __restrict__ A, const float* __restrict__ Bm,
    const float* __restrict__ bias, float* __restrict__ C,
    int M, int N, int K)
{
    __shared__ __align__(16) float As[BKt][BM + 4];
    __shared__ __align__(16) float Bs[BKt][BN + 4];
    int tid = threadIdx.x;
    int tx = tid & 15, ty = tid >> 4;
    int n0 = blockIdx.x * BN, m0 = blockIdx.y * BM;

    unsigned long long acc[4][8];
#pragma unroll
    for (int i = 0; i < 4; i++)
#pragma unroll
        for (int j = 0; j < 8; j++) acc[i][j] = 0ull;

    for (int kk = 0; kk < K; kk += BKt) {
#pragma unroll
        for (int q = 0; q < 2; q++) {
            int s = tid + q * 256;
            int row = s >> 2, kq = s & 3;
            float4 va = make_float4(0.f, 0.f, 0.f, 0.f);
            int gm = m0 + row;
            if (gm < M) va = *(const float4*)(A + (size_t)gm * K + kk + kq * 4);
            As[kq * 4 + 0][row] = va.x; As[kq * 4 + 1][row] = va.y;
            As[kq * 4 + 2][row] = va.z; As[kq * 4 + 3][row] = va.w;
            float4 vb = make_float4(0.f, 0.f, 0.f, 0.f);
            int gn = n0 + row;
            if (gn < N) vb = *(const float4*)(Bm + (size_t)gn * K + kk + kq * 4);
            Bs[kq * 4 + 0][row] = vb.x; Bs[kq * 4 + 1][row] = vb.y;
            Bs[kq * 4 + 2][row] = vb.z; Bs[kq * 4 + 3][row] = vb.w;
        }
        __syncthreads();
#pragma unroll
        for (int k = 0; k < BKt; k++) {
            const unsigned long long* ap =
                (const unsigned long long*)&As[k][ty * 8];
            unsigned long long a0 = ap[0], a1 = ap[1], a2 = ap[2], a3 = ap[3];
            float4 b0 = *(const float4*)&Bs[k][tx * 8];
            float4 b1 = *(const float4*)&Bs[k][tx * 8 + 4];
            float bv[8] = {b0.x, b0.y, b0.z, b0.w, b1.x, b1.y, b1.z, b1.w};
#pragma unroll
            for (int j = 0; j < 8; j++) {
                unsigned long long bd = pk2(bv[j], bv[j]);
                acc[0][j] = f2fma(a0, bd, acc[0][j]);
                acc[1][j] = f2fma(a1, bd, acc[1][j]);
                acc[2][j] = f2fma(a2, bd, acc[2][j]);
                acc[3][j] = f2fma(a3, bd, acc[3][j]);
            }
        }
        __syncthreads();
    }

    float bvv[8];
#pragma unroll
    for (int j = 0; j < 8; j++) {
        int gc = n0 + tx * 8 + j;
        bvv[j] = (gc < N) ? bias[gc] : 0.f;
    }
    int gc0 = n0 + tx * 8;
    bool c0ok = (gc0 < N), c1ok = (gc0 + 4 < N);
#pragma unroll
    for (int ip = 0; ip < 4; ip++) {
        float lo[8], hi[8];
#pragma unroll
        for (int j = 0; j < 8; j++) {
            upk(acc[ip][j], lo[j], hi[j]);
            lo[j] += bvv[j]; hi[j] += bvv[j];
        }
        int r0 = m0 + ty * 8 + 2 * ip;
        if (r0 < M) {
            float* cp = C + (size_t)r0 * N + gc0;
            if (c0ok) *(float4*)cp       = make_float4(lo[0], lo[1], lo[2], lo[3]);
            if (c1ok) *(float4*)(cp + 4) = make_float4(lo[4], lo[5], lo[6], lo[7]);
        }
        if (r0 + 1 < M) {
            float* cp = C + (size_t)(r0 + 1) * N + gc0;
            if (c0ok) *(float4*)cp       = make_float4(hi[0], hi[1], hi[2], hi[3]);
            if (c1ok) *(float4*)(cp + 4) = make_float4(hi[4], hi[5], hi[6], hi[7]);
        }
    }
}

// ----------------------- fp16 HMMA GEMM (rec head) --------------------------
// Block tile 128x128, K-chunk 32 double-buffered (cp.async), 8 warps 2x4,
// warp tile 64x32, ldmatrix.x4 from CONFLICT-FREE swizzled smem.  Occ 2.
// Swizzle: slot = ch ^ ((row>>1)&3).  An ldmatrix phase spans 8 consecutive
// rows; offsets cover all eight distinct 16B slots of the 128B bank window
// (old ch^(row&3) repeated with period 4 -> 2-way conflict every phase).
__global__ void __launch_bounds__(256, 2) gemm_h_k(
    const __half* __restrict__ A, const __half* __restrict__ Bm,
    const float* __restrict__ bias, float* __restrict__ C, int N)
{
    const int K = 256;
    __shared__ __align__(16) __half Asm[2][128 * 32];
    __shared__ __align__(16) __half Bsm[2][128 * 32];

    int tid = threadIdx.x, lane = tid & 31, wid = tid >> 5;
    int wm = wid & 1, wn = wid >> 1;
    int m0 = blockIdx.y * 128, n0 = blockIdx.x * 128;

    float c[4][4][4];
#pragma unroll
    for (int mi = 0; mi < 4; mi++)
#pragma unroll
        for (int ni = 0; ni < 4; ni++)
#pragma unroll
            for (int r = 0; r < 4; r++) c[mi][ni][r] = 0.f;

    int lr = tid >> 1;
    int lc0 = (tid & 1) * 2;
    int bn = n0 + lr; if (bn > N - 1) bn = N - 1;
    const __half* Abase = A + (size_t)(m0 + lr) * K;
    const __half* Bbase = Bm + (size_t)bn * K;

#define SOFF(r, ch) ((r) * 32 + (((ch) ^ (((r) >> 1) & 3)) << 3))

#pragma unroll
    for (int c2 = 0; c2 < 2; c2++) {
        int ch = lc0 + c2;
        cp16(smaddr(&Asm[0][SOFF(lr, ch)]), Abase + ch * 8);
        cp16(smaddr(&Bsm[0][SOFF(lr, ch)]), Bbase + ch * 8);
    }
    asm volatile("cp.async.commit_group;");

    int buf = 0;
    for (int kc = 0; kc < K / 32; kc++) {
        asm volatile("cp.async.wait_group 0;");
        __syncthreads();
        if (kc + 1 < K / 32) {
            int kk = (kc + 1) * 32;
#pragma unroll
            for (int c2 = 0; c2 < 2; c2++) {
                int ch = lc0 + c2;
                cp16(smaddr(&Asm[buf ^ 1][SOFF(lr, ch)]), Abase + kk + ch * 8);
                cp16(smaddr(&Bsm[buf ^ 1][SOFF(lr, ch)]), Bbase + kk + ch * 8);
            }
            asm volatile("cp.async.commit_group;");
        }
#pragma unroll
        for (int ks = 0; ks < 2; ks++) {
            unsigned a[4][4], b[2][4];
#pragma unroll
            for (int mi = 0; mi < 4; mi++) {
                int row = wm * 64 + mi * 16 + (lane & 15);
                int ch  = ks * 2 + (lane >> 4);
                uint32_t ad = smaddr(&Asm[buf][SOFF(row, ch)]);
                asm volatile(
                    "ldmatrix.sync.aligned.m8n8.x4.shared.b16 {%0,%1,%2,%3}, [%4];"
                    : "=r"(a[mi][0]), "=r"(a[mi][1]), "=r"(a[mi][2]), "=r"(a[mi][3])
                    : "r"(ad));
            }
#pragma unroll
            for (int nj = 0; nj < 2; nj++) {
                int row = wn * 32 + nj * 16 + (lane & 7) + (lane >> 4) * 8;
                int ch  = ks * 2 + ((lane >> 3) & 1);
                uint32_t bd = smaddr(&Bsm[buf][SOFF(row, ch)]);
                asm volatile(
                    "ldmatrix.sync.aligned.m8n8.x4.shared.b16 {%0,%1,%2,%3}, [%4];"
                    : "=r"(b[nj][0]), "=r"(b[nj][1]), "=r"(b[nj][2]), "=r"(b[nj][3])
                    : "r"(bd));
            }
#pragma unroll
            for (int mi = 0; mi < 4; mi++)
#pragma unroll
                for (int ni = 0; ni < 4; ni++) {
                    unsigned bb0 = b[ni >> 1][(ni & 1) * 2];
                    unsigned bb1 = b[ni >> 1][(ni & 1) * 2 + 1];
                    asm volatile(
                        "mma.sync.aligned.m16n8k16.row.col.f32.f16.f16.f32 "
                        "{%0,%1,%2,%3}, {%4,%5,%6,%7}, {%8,%9}, {%0,%1,%2,%3};\n"
                        : "+f"(c[mi][ni][0]), "+f"(c[mi][ni][1]),
                          "+f"(c[mi][ni][2]), "+f"(c[mi][ni][3])
                        : "r"(a[mi][0]), "r"(a[mi][1]), "r"(a[mi][2]), "r"(a[mi][3]),
                          "r"(bb0), "r"(bb1));
                }
        }
        buf ^= 1;
    }

    int g = lane >> 2, q = lane & 3;
#pragma unroll
    for (int ni = 0; ni < 4; ni++) {
        int ncol = n0 + wn * 32 + ni * 8 + 2 * q;
        if (ncol >= N) continue;
        float b0 = bias[ncol], b1 = bias[ncol + 1];
#pragma unroll
        for (int mi = 0; mi < 4; mi++) {
            int r0 = m0 + wm * 64 + mi * 16 + g;
            *(float2*)(C + (size_t)r0 * N + ncol) =
                make_float2(c[mi][ni][0] + b0, c[mi][ni][1] + b1);
            *(float2*)(C + (size_t)(r0 + 8) * N + ncol) =
                make_float2(c[mi][ni][2] + b0, c[mi][ni][3] + b1);
        }
    }
#undef SOFF
}

// ---------------------------- GRU recurrence --------------------------------
// Split-K: warp w = (output block g = w>>2, chunk c = w&3).
// Phase 1: 4 outputs x 32 elems per thread (64 f2fma), chunk-local h reads.
// Phase 2 (warps 0-7): lanes 0-15 gate r of j=w*16+lane; lanes 16-31 z AND n
// of same j (r via shfl.xor 16).  2 barriers/step.
__global__ void __launch_bounds__(384, 1) recur_k(
    const float* __restrict__ GI,    // [B*T][768] or [B][768] (gi_const)
    const float* __restrict__ Whh,   // [2][384][128]
    const float* __restrict__ bhh,   // [2][384]
    float* __restrict__ Yf,          // fp32 outputs [B*T][256] or nullptr
    __half* __restrict__ Yh,         // fp16 outputs or nullptr
    float* __restrict__ Hout,        // [B][512]
    int loff, int gi_const)
{
    int b = blockIdx.x, d = blockIdx.y;
    int o = threadIdx.x;
    int w = o >> 5, l = o & 31;
    int g = w >> 2, c = w & 3;

    __shared__ __align__(16) float sh_h[128];
    __shared__ float part[4][384];

    unsigned long long w2[4][16];
#pragma unroll
    for (int k = 0; k < 4; k++) {
        int row = d * G3H + 128 * g + 32 * k + l;
        const float2* wr = (const float2*)(Whh + (size_t)row * H_) + 16 * c;
#pragma unroll
        for (int e = 0; e < 16; e++) {
            float2 v = wr[e];
            w2[k][e] = pk2(v.x, v.y);
        }
    }

    bool p2  = (w < 8);
    bool isn = p2 && (l >= 16);
    int  j2  = w * 16 + (l & 15);
    int rowR = d * G3H + j2;
    int rowZ = rowR + 128;
    int rowN = rowR + 256;

    float bhR = 0.f, bhZ = 0.f, bhN = 0.f;
    if (p2) {
        if (!isn) bhR = bhh[rowR];
        else { bhZ = bhh[rowZ]; bhN = bhh[rowN]; }
    }

    if (o < 128) sh_h[o] = 0.f;
    __syncthreads();

    float giR = 0.f, giZ = 0.f, giN = 0.f;
    if (p2) {
        size_t base;
        if (gi_const) base = (size_t)b * 768;
        else { int t0 = d ? (T_ - 1) : 0; base = (size_t)(b * T_ + t0) * 768; }
        if (!isn) giR = GI[base + rowR];
        else { giZ = GI[base + rowZ]; giN = GI[base + rowN]; }
    }

    for (int s = 0; s < T_; s++) {
        int t = d ? (T_ - 1 - s) : s;
        float gR = giR, gZ = giZ, gN = giN;
        if (p2 && !gi_const && s + 1 < T_) {
            int t1 = d ? (T_ - 2 - s) : (s + 1);
            size_t base = (size_t)(b * T_ + t1) * 768;
            if (!isn) giR = GI[base + rowR];
            else { giZ = GI[base + rowZ]; giN = GI[base + rowN]; }
        }

        const ulonglong2* hc = (const ulonglong2*)(sh_h + 32 * c);
        unsigned long long a0 = 0ull, a1 = 0ull, a2 = 0ull, a3 = 0ull;
#pragma unroll
        for (int q = 0; q < 8; q++) {
            ulonglong2 v = hc[q];
            a0 = f2fma(w2[0][2 * q], v.x, a0);
            a1 = f2fma(w2[1][2 * q], v.x, a1);
            a2 = f2fma(w2[2][2 * q], v.x, a2);
            a3 = f2fma(w2[3][2 * q], v.x, a3);
            a0 = f2fma(w2[0][2 * q + 1], v.y, a0);
            a1 = f2fma(w2[1][2 * q + 1], v.y, a1);
            a2 = f2fma(w2[2][2 * q + 1], v.y, a2);
            a3 = f2fma(w2[3][2 * q + 1], v.y, a3);
        }
        float x, y;
        upk(a0, x, y); part[c][128 * g + l]      = x + y;
        upk(a1, x, y); part[c][128 * g + 32 + l] = x + y;
        upk(a2, x, y); part[c][128 * g + 64 + l] = x + y;
        upk(a3, x, y); part[c][128 * g + 96 + l] = x + y;
        __syncthreads();

        if (p2) {
            float rv = 0.f;
            if (!isn) {
                float sr = part[0][j2] + part[1][j2] + part[2][j2] + part[3][j2];
                rv = fast_sigm(gR + sr + bhR);
            }
            float rx = __shfl_xor_sync(0xffffffffu, rv, 16);
            if (isn) {
                int oz = 128 + j2, on = 256 + j2;
                float sz = part[0][oz] + part[1][oz] + part[2][oz] + part[3][oz];
                float sn = part[0][on] + part[1][on] + part[2][on] + part[3][on];
                float z = fast_sigm(gZ + sz + bhZ);
                float n = fast_tanh(gN + rx * (sn + bhN));
                float hold = sh_h[j2];
                float hn = (1.f - z) * n + z * hold;
                sh_h[j2] = hn;
                int idx = (b * T_ + t) * 256 + d * H_ + j2;
                if (Yf) Yf[idx] = hn;
                if (Yh) Yh[idx] = __float2half(hn);
            }
        }
        __syncthreads();
    }
    if (isn) Hout[(size_t)b * 512 + loff + d * H_ + j2] = sh_h[j2];
}

// -------------------------------- fc head -----------------------------------
__global__ void fc_k(const float* __restrict__ ench,
                     const float* __restrict__ dech,
                     const float* __restrict__ W,
                     const float* __restrict__ bias,
                     float* __restrict__ out)
{
    int b = blockIdx.x;
    __shared__ float feat[1024];
    int tid = threadIdx.x;
    for (int i = tid; i < 512; i += 256) {
        feat[i]       = ench[b * 512 + i];
        feat[512 + i] = dech[b * 512 + i];
    }
    __syncthreads();
    int w = tid >> 5, lane = tid & 31;
    for (int c = w; c < NCLS; c += 8) {
        float acc = 0.f;
        for (int k = lane; k < 1024; k += 32)
            acc = fmaf(feat[k], W[c * 1024 + k], acc);
#pragma unroll
        for (int off = 16; off; off >>= 1)
            acc += __shfl_down_sync(0xffffffffu, acc, off);
        if (lane == 0) out[b * NCLS + c] = acc + bias[c];
    }
}

// ------------------------------- launcher -----------------------------------
extern "C" void kernel_launch(void* const* d_in, const int* in_sizes, int n_in,
                              void* d_out, int out_size)
{
    const void*  x    = d_in[0];
    const float* emb  = (const float*)d_in[1];
    const float* eWih0 = (const float*)d_in[2];
    const float* eWhh0 = (const float*)d_in[3];
    const float* ebih0 = (const float*)d_in[4];
    const float* ebhh0 = (const float*)d_in[5];
    const float* eWih1 = (const float*)d_in[6];
    const float* eWhh1 = (const float*)d_in[7];
    const float* ebih1 = (const float*)d_in[8];
    const float* ebhh1 = (const float*)d_in[9];
    const float* dWih0 = (const float*)d_in[10];
    const float* dWhh0 = (const float*)d_in[11];
    const float* dbih0 = (const float*)d_in[12];
    const float* dbhh0 = (const float*)d_in[13];
    const float* dWih1 = (const float*)d_in[14];
    const float* dWhh1 = (const float*)d_in[15];
    const float* dbih1 = (const float*)d_in[16];
    const float* dbhh1 = (const float*)d_in[17];
    const float* fcW   = (const float*)d_in[18];
    const float* fcb   = (const float*)d_in[19];
    const float* recW  = (const float*)d_in[20];
    const float* recb  = (const float*)d_in[21];

    float* out = (float*)d_out;          // [64,20]
    float* rec = out + B_ * NCLS;        // [64,100,10000]

    float *pE, *pGI, *pGIc, *pY0, *pench, *pdech;
    __half *pRECh, *pWh;
    cudaGetSymbolAddress((void**)&pE,    g_E);
    cudaGetSymbolAddress((void**)&pGI,   g_GI);
    cudaGetSymbolAddress((void**)&pGIc,  g_GIc);
    cudaGetSymbolAddress((void**)&pY0,   g_Y0);
    cudaGetSymbolAddress((void**)&pRECh, g_RECh);
    cudaGetSymbolAddress((void**)&pWh,   g_Wh);
    cudaGetSymbolAddress((void**)&pench, g_ench);
    cudaGetSymbolAddress((void**)&pdech, g_dech);

    detect_k<<<1, 64>>>((const unsigned int*)x);
    embed_k<<<(BT * 32 + 255) / 256, 256>>>(x, emb);

    // encoder layer 0
    gemm_bt_k<<<dim3(6, 50), 256>>>(pE, eWih0, ebih0, pGI, BT, 768, 128);
    recur_k<<<dim3(B_, 2), 384>>>(pGI, eWhh0, ebhh0, pY0, nullptr, pench, 0, 0);
    // encoder layer 1 (only final hidden needed)
    gemm_bt_k<<<dim3(6, 50), 256>>>(pY0, eWih1, ebih1, pGI, BT, 768, 256);
    recur_k<<<dim3(B_, 2), 384>>>(pGI, eWhh1, ebhh1, nullptr, nullptr, pench, 256, 0);
    // decoder layer 0 (broadcast input -> gi constant per step)
    gemm_bt_k<<<dim3(6, 1), 256>>>(pench, dWih0, dbih0, pGIc, B_, 768, 512);
    recur_k<<<dim3(B_, 2), 384>>>(pGIc, dWhh0, dbhh0, pY0, nullptr, pdech, 0, 1);
    // decoder layer 1 (outputs = rec_seq, written in fp16 for the HMMA GEMM)
    gemm_bt_k<<<dim3(6, 50), 256>>>(pY0, dWih1, dbih1, pGI, BT, 768, 256);
    recur_k<<<dim3(B_, 2), 384>>>(pGI, dWhh1, dbhh1, nullptr, pRECh, pdech, 256, 0);

    // heads
    cvt_k<<<(VOCAB * 128 + 255) / 256, 256>>>(recW, pWh, VOCAB * 128);
    fc_k<<<B_, 256>>>(pench, pdech, fcW, fcb, out);
    gemm_h_k<<<dim3((VOCAB + 127) / 128, BT / 128), 256>>>(
        pRECh, pWh, recb, rec, VOCAB);
}